// round 9
// baseline (speedup 1.0000x reference)
#include <cuda_runtime.h>
#include <cstddef>

#define B_   32
#define T_   128
#define P_   4
#define DIN_ 512
#define H_   512
#define C_   4096
#define G_   16384
#define NBLK 128
#define NT   512

typedef unsigned long long ull;

__device__ float g_pi  [(size_t)B_ * T_ * G_];
__device__ float g_mem [(size_t)T_ * C_ * B_];
__device__ float g_st  [(size_t)T_ * H_ * B_];
__device__ float g_a2  [C_ * B_];
__device__ float g_pst2[H_ * B_];
__device__ float g_hp  [NBLK * 1024];
__device__ int   g_cntA[T_ * 8];
__device__ int   g_cntB[T_ * 16];
__device__ int   g_done[T_];

__device__ __forceinline__ ull pack2(float a, float b) {
    ull d;
    unsigned x = __float_as_uint(a), y = __float_as_uint(b);
    asm("mov.b64 %0, {%1,%2};" : "=l"(d) : "r"(x), "r"(y));
    return d;
}
__device__ __forceinline__ ull dup2(float a) { return pack2(a, a); }
__device__ __forceinline__ void unpack2(ull s, float& a, float& b) {
    unsigned x, y;
    asm("mov.b64 {%0,%1}, %2;" : "=r"(x), "=r"(y) : "l"(s));
    a = __uint_as_float(x); b = __uint_as_float(y);
}
__device__ __forceinline__ ull fma2(ull a, ull b, ull c) {
    ull d;
    asm("fma.rn.f32x2 %0, %1, %2, %3;" : "=l"(d) : "l"(a), "l"(b), "l"(c));
    return d;
}
__device__ __forceinline__ float sigmoidf(float x) { return 1.0f / (1.0f + __expf(-x)); }

__device__ __forceinline__ int ld_acq(const int* p) {
    int v;
    asm volatile("ld.acquire.gpu.global.b32 %0, [%1];" : "=r"(v) : "l"(p) : "memory");
    return v;
}
__device__ __forceinline__ int atom_add_acqrel(int* p, int v) {
    int old;
    asm volatile("atom.acq_rel.gpu.global.add.s32 %0, [%1], %2;"
                 : "=r"(old) : "l"(p), "r"(v) : "memory");
    return old;
}
__device__ __forceinline__ void cp16(float* s, const float* g) {
    unsigned sa = (unsigned)__cvta_generic_to_shared(s);
    asm volatile("cp.async.cg.shared.global [%0], [%1], 16;" :: "r"(sa), "l"(g));
}
#define CP_COMMIT() asm volatile("cp.async.commit_group;")
#define CP_WAIT0()  asm volatile("cp.async.wait_group 0;")

__global__ void init_sig() {
    int i = blockIdx.x * blockDim.x + threadIdx.x;
    if (i < T_ * 8)  g_cntA[i] = 0;
    if (i < T_ * 16) g_cntB[i] = 0;
    if (i < T_)      g_done[i] = 0;
}

// =====================================================================
// proj_in = x @ W_in^T (known-good)
// =====================================================================
__global__ void __launch_bounds__(256) proj_in_kernel(const float* __restrict__ x,
                                                      const float* __restrict__ W_in) {
    __shared__ __align__(16) float As[16][128];
    __shared__ __align__(16) float Bs[16][128];
    const int tid = threadIdx.x;
    const int m0 = blockIdx.y * 128;
    const int n0 = blockIdx.x * 128;
    const int tm = tid >> 4;
    const int tn = tid & 15;

    ull acc[8][4];
#pragma unroll
    for (int i = 0; i < 8; i++)
#pragma unroll
        for (int j = 0; j < 4; j++) acc[i][j] = 0ull;

    for (int kk = 0; kk < DIN_; kk += 16) {
#pragma unroll
        for (int r = 0; r < 2; r++) {
            int f = tid + r * 256;
            int row = f >> 2;
            int kq = f & 3;
            float4 va = *(const float4*)&x[(size_t)(m0 + row) * DIN_ + kk + kq * 4];
            As[kq * 4 + 0][row] = va.x; As[kq * 4 + 1][row] = va.y;
            As[kq * 4 + 2][row] = va.z; As[kq * 4 + 3][row] = va.w;
            float4 vb = *(const float4*)&W_in[(size_t)(n0 + row) * DIN_ + kk + kq * 4];
            Bs[kq * 4 + 0][row] = vb.x; Bs[kq * 4 + 1][row] = vb.y;
            Bs[kq * 4 + 2][row] = vb.z; Bs[kq * 4 + 3][row] = vb.w;
        }
        __syncthreads();
#pragma unroll
        for (int k = 0; k < 16; k++) {
            float4 a0 = *(const float4*)&As[k][tm * 8];
            float4 a1 = *(const float4*)&As[k][tm * 8 + 4];
            ulonglong2 b0 = *(const ulonglong2*)&Bs[k][tn * 8];
            ulonglong2 b1 = *(const ulonglong2*)&Bs[k][tn * 8 + 4];
            float av[8] = {a0.x, a0.y, a0.z, a0.w, a1.x, a1.y, a1.z, a1.w};
#pragma unroll
            for (int i = 0; i < 8; i++) {
                ull pa = dup2(av[i]);
                acc[i][0] = fma2(pa, b0.x, acc[i][0]);
                acc[i][1] = fma2(pa, b0.y, acc[i][1]);
                acc[i][2] = fma2(pa, b1.x, acc[i][2]);
                acc[i][3] = fma2(pa, b1.y, acc[i][3]);
            }
        }
        __syncthreads();
    }
#pragma unroll
    for (int i = 0; i < 8; i++) {
        float o[8];
        unpack2(acc[i][0], o[0], o[1]); unpack2(acc[i][1], o[2], o[3]);
        unpack2(acc[i][2], o[4], o[5]); unpack2(acc[i][3], o[6], o[7]);
        size_t base = (size_t)(m0 + tm * 8 + i) * G_ + n0 + tn * 8;
        *(float4*)&g_pi[base]     = make_float4(o[0], o[1], o[2], o[3]);
        *(float4*)&g_pi[base + 4] = make_float4(o[4], o[5], o[6], o[7]);
    }
}

// =====================================================================
// scan: 128 blocks x 512 threads. lane = batch, warp-autonomous GEMM.
// smem (floats):
//   [0,16384)      s_pst : [kpair][b*2+par]       (phase A activations)
//   [16384,32768)  strm  : 16 warps x 2 slots x 512  (weights; B: reduce buf)
//   [32768,36992)  s_pi  : 128 rows x 33
//   [36992,54400)  sWpB  : 512 c x 34 (persistent W_proj slice)
//   [54400,54404)  s_flag
// =====================================================================
#define SM_PST 0
#define SM_STR 16384
#define SM_PI  32768
#define SM_FLG 54400
#define SM_WPB 36992
#define SMEM_FLOATS 54404

// per-warp weight chunk load: 8 j-rows x 64 k  (4 float4 per lane)
__device__ __forceinline__ void ldgW(float4* wreg, const float* __restrict__ W_state,
                                     int bid, int w, int lane, int ch) {
    const int jj = lane >> 2;                 // 0..7 = ci*4+g
    const int q  = lane & 3;
    const int jrow = (jj & 3) * C_ + bid * 32 + 2 * w + (jj >> 2);
    const float* base = &W_state[(size_t)jrow * H_ + ch * 64];
#pragma unroll
    for (int r = 0; r < 4; r++)
        wreg[r] = __ldg((const float4*)(base + (q + r * 4) * 4));
}
__device__ __forceinline__ void stsW(float* sbuf, const float4* wreg, int lane) {
    const int jj = lane >> 2;
    const int q  = lane & 3;
#pragma unroll
    for (int r = 0; r < 4; r++) {
        int quad = q + r * 4;                 // k-quad within chunk (0..15)
        *(float2*)&sbuf[(quad * 2    ) * 16 + jj * 2] = make_float2(wreg[r].x, wreg[r].y);
        *(float2*)&sbuf[(quad * 2 + 1) * 16 + jj * 2] = make_float2(wreg[r].z, wreg[r].w);
    }
}

__global__ void __launch_bounds__(NT, 1) scan_kernel(
    const int*   __restrict__ prev_idx,
    const float* __restrict__ prev_w,
    const float* __restrict__ W_state,
    const float* __restrict__ b_state,
    const float* __restrict__ W_proj,
    float* __restrict__ out)
{
    extern __shared__ __align__(16) float sm[];
    float* s_pst  = sm + SM_PST;
    float* s_strm = sm + SM_STR;
    float* s_pi   = sm + SM_PI;
    float* sWpB   = sm + SM_WPB;
    int*   s_flag = (int*)(sm + SM_FLG);

    const int tid  = threadIdx.x;
    const int bid  = blockIdx.x;
    const int w    = tid >> 5;
    const int b    = tid & 31;
    const int ht   = bid >> 3;
    const int ks   = bid & 7;
    const int ksA  = bid >> 4;
    float* myStrm  = s_strm + w * 1024;      // 2 slots x 512 floats

    // persistent W_proj slice: sWpB[c*34 + h_local]
    for (int r = 0; r < 32; r++) {
        int e  = r * NT + tid;
        int hl = e >> 9;
        int c  = e & 511;
        sWpB[c * 34 + hl] = __ldg(&W_proj[(size_t)(ht * 32 + hl) * C_ + ks * 512 + c]);
    }
    const int cA = bid * 32 + w * 2;
    float bst[2][4];
#pragma unroll
    for (int ci = 0; ci < 2; ci++)
#pragma unroll
        for (int g = 0; g < 4; g++)
            bst[ci][g] = __ldg(&b_state[g * C_ + cA + ci]);
    __syncthreads();

    for (int t = 0; t < T_; t++) {
        // ---- step-independent loads (issue before any wait) ----
        int idxA[P_]; float wA[P_];
#pragma unroll
        for (int p = 0; p < P_; p++) {
            idxA[p] = __ldg(&prev_idx[(b * T_ + t) * P_ + p]);
            wA[p]   = __ldg(&prev_w [(b * T_ + t) * P_ + p]);
        }
        float pmv[2][P_];
#pragma unroll
        for (int ci = 0; ci < 2; ci++)
#pragma unroll
            for (int p = 0; p < P_; p++)
                pmv[ci][p] = g_mem[((size_t)idxA[p] * C_ + cA + ci) * B_ + b];
#pragma unroll
        for (int r = 0; r < 8; r++) {
            int e  = r * NT + tid;
            int bb = e >> 7;
            int gg = (e >> 5) & 3;
            int cl = e & 31;
            s_pi[(gg * 32 + cl) * 33 + bb] =
                __ldg(&g_pi[((size_t)(bb * T_ + t)) * G_ + gg * C_ + bid * 32 + cl]);
        }

        ull acc[8];
#pragma unroll
        for (int i = 0; i < 8; i++) acc[i] = 0ull;

        if (t > 0) {
            float4 wreg[4];
            ldgW(wreg, W_state, bid, w, b, 0);   // chunk0 prefetch (no dependence)
            if (tid == 0) { while (ld_acq(&g_done[t - 1]) != 16) __nanosleep(40); }
            __syncthreads();                      // release pst; also orders s_pi
            // stage pooled state (interleaved pairs), L1-bypassing
#pragma unroll
            for (int r = 0; r < 8; r++) {
                int e = r * NT + tid;
                cp16(s_pst + e * 4, g_pst2 + e * 4);
            }
            CP_COMMIT();
            stsW(myStrm, wreg, b);
            CP_WAIT0();
            __syncthreads();                      // pst visible to all warps

            // ---- warp-autonomous double-buffered GEMM, no block barriers ----
#pragma unroll 1
            for (int ch = 0; ch < 8; ch++) {
                float* buf = myStrm + (ch & 1) * 512;
                if (ch < 7) ldgW(wreg, W_state, bid, w, b, ch + 1);
                __syncwarp();
#pragma unroll 4
                for (int kp = 0; kp < 32; kp++) {
                    ull pa = *(const ull*)&s_pst[((ch * 32 + kp) * 32 + b) * 2];
                    const ulonglong2* wp = (const ulonglong2*)&buf[kp * 16];
                    ulonglong2 q0 = wp[0], q1 = wp[1];
                    acc[0] = fma2(q0.x, pa, acc[0]); acc[1] = fma2(q0.y, pa, acc[1]);
                    acc[2] = fma2(q1.x, pa, acc[2]); acc[3] = fma2(q1.y, pa, acc[3]);
                    ulonglong2 q2 = wp[2], q3 = wp[3];
                    acc[4] = fma2(q2.x, pa, acc[4]); acc[5] = fma2(q2.y, pa, acc[5]);
                    acc[6] = fma2(q3.x, pa, acc[6]); acc[7] = fma2(q3.y, pa, acc[7]);
                }
                __syncwarp();
                if (ch < 7) stsW(myStrm + ((ch + 1) & 1) * 512, wreg, b);
            }
        } else {
            __syncthreads();                      // t==0: order s_pi staging (R7 lesson)
        }

        // ---- A epilogue: gates + mem + a2 ----
        {
            float a2v[2];
#pragma unroll
            for (int ci = 0; ci < 2; ci++) {
                float pmem = 0.f;
#pragma unroll
                for (int p = 0; p < P_; p++) pmem += wA[p] * pmv[ci][p];
                float gv[4];
#pragma unroll
                for (int g = 0; g < 4; g++) {
                    float lo, hi;
                    unpack2(acc[ci * 4 + g], lo, hi);
                    gv[g] = lo + hi + s_pi[(g * 32 + w * 2 + ci) * 33 + b] + bst[ci][g];
                }
                float ig = sigmoidf(gv[0]);
                float fg = sigmoidf(gv[1]);
                float mi = tanhf(gv[2]);
                float og = sigmoidf(gv[3]);
                float mem = fminf(3.f, fmaxf(-3.f, ig * mi + fg * pmem));
                g_mem[((size_t)t * C_ + cA + ci) * B_ + b] = mem;
                a2v[ci] = og * tanhf(mem);
            }
            *(float2*)&g_a2[(bid * 16 + w) * 64 + b * 2] = make_float2(a2v[0], a2v[1]);
        }
        __syncthreads();
        if (tid == 0) atom_add_acqrel(&g_cntA[t * 8 + ksA], 1);

        // ================= Phase B: direct-LDG split-K projection =================
        if (tid == 0) { while (ld_acq(&g_cntA[t * 8 + ks]) != 16) __nanosleep(32); }
        __syncthreads();

        ull pac[8];
#pragma unroll
        for (int i = 0; i < 8; i++) pac[i] = 0ull;
        const int hhalf = w & 1;
        const int cch   = w >> 1;
        const float* aBase = g_a2 + (size_t)(ks * 256 + cch * 32) * 64 + b * 2;
#pragma unroll 4
        for (int cp = 0; cp < 32; cp++) {
            float2 av = __ldcg((const float2*)(aBase + cp * 64));
            ull dlo = dup2(av.x), dhi = dup2(av.y);
            const int c0 = (cch * 32 + cp) * 2;
#pragma unroll
            for (int hp = 0; hp < 8; hp++) {
                ull w0 = *(const ull*)&sWpB[c0 * 34 + (hhalf * 8 + hp) * 2];
                ull w1 = *(const ull*)&sWpB[(c0 + 1) * 34 + (hhalf * 8 + hp) * 2];
                pac[hp] = fma2(w0, dlo, pac[hp]);
                pac[hp] = fma2(w1, dhi, pac[hp]);
            }
        }
        // in-block reduce over 16 warps (reduce buf aliases stream region)
        float* red = s_strm;
        __syncwarp();
#pragma unroll
        for (int hp = 0; hp < 8; hp++)
            *(ull*)&red[((w * 8 + hp) * 32 + b) * 2] = pac[hp];
        __syncthreads();
#pragma unroll
        for (int r2 = 0; r2 < 2; r2++) {
            int o  = r2 * NT + tid;
            int hl = o >> 5, bb = o & 31;
            int ph   = hl >> 4;
            int hpin = (hl >> 1) & 7;
            int par  = hl & 1;
            float s = 0.f;
#pragma unroll
            for (int q = 0; q < 8; q++)
                s += red[(((q * 2 + ph) * 8 + hpin) * 32 + bb) * 2 + par];
            g_hp[bid * 1024 + hl * 32 + bb] = s;
        }
        __syncthreads();
        if (tid == 0) s_flag[0] = atom_add_acqrel(&g_cntB[t * 16 + ht], 1);
        __syncthreads();

        // ================= Phase C: last k-split block of h-group finalizes =================
        if (s_flag[0] == 7) {
#pragma unroll
            for (int r2 = 0; r2 < 2; r2++) {
                int o  = r2 * NT + tid;
                int hl = o >> 5, bb = o & 31;
                float s = 0.f;
#pragma unroll
                for (int q = 0; q < 8; q++)
                    s += __ldcg(&g_hp[(ht * 8 + q) * 1024 + hl * 32 + bb]);
                s = fminf(3.f, fmaxf(-3.f, s));
                const int hg = ht * 32 + hl;
                g_st[((size_t)t * H_ + hg) * B_ + bb] = s;
                out[((size_t)bb * T_ + t) * H_ + hg]  = s;
                if (t < T_ - 1) {
                    float pv = 0.f;
#pragma unroll
                    for (int p = 0; p < P_; p++) {
                        int ip   = __ldg(&prev_idx[(bb * T_ + t + 1) * P_ + p]);
                        float wv = __ldg(&prev_w [(bb * T_ + t + 1) * P_ + p]);
                        float v  = (ip == t) ? s : __ldcg(&g_st[((size_t)ip * H_ + hg) * B_ + bb]);
                        pv += wv * v;
                    }
                    g_pst2[(hg >> 1) * 64 + bb * 2 + (hg & 1)] = pv;
                }
            }
            __syncthreads();
            if (tid == 0) atom_add_acqrel(&g_done[t], 1);
        }
        __syncthreads();
    }
}

extern "C" void kernel_launch(void* const* d_in, const int* in_sizes, int n_in,
                              void* d_out, int out_size) {
    const float* x        = (const float*)d_in[0];
    const int*   prev_idx = (const int*)  d_in[1];
    const float* prev_w   = (const float*)d_in[2];
    const float* W_in     = (const float*)d_in[3];
    const float* W_state  = (const float*)d_in[4];
    const float* b_state  = (const float*)d_in[5];
    const float* W_proj   = (const float*)d_in[6];
    float* out = (float*)d_out;
    (void)in_sizes; (void)n_in; (void)out_size;

    const int smem = SMEM_FLOATS * (int)sizeof(float);
    cudaFuncSetAttribute(scan_kernel, cudaFuncAttributeMaxDynamicSharedMemorySize, smem);

    init_sig<<<2, 1024>>>();
    proj_in_kernel<<<dim3(G_ / 128, (B_ * T_) / 128), 256>>>(x, W_in);
    scan_kernel<<<NBLK, NT, smem>>>(prev_idx, prev_w, W_state, b_state, W_proj, out);
}

// round 10
// speedup vs baseline: 1.0447x; 1.0447x over previous
#include <cuda_runtime.h>
#include <cstddef>

#define B_   32
#define T_   128
#define P_   4
#define DIN_ 512
#define H_   512
#define C_   4096
#define G_   16384
#define NBLK 128
#define NT   512

typedef unsigned long long ull;

__device__ float g_pi  [(size_t)B_ * T_ * G_];
__device__ float g_mem [(size_t)T_ * C_ * B_];
__device__ float g_st  [(size_t)T_ * H_ * B_];
__device__ float g_a2  [C_ * B_];
__device__ float g_pst2[H_ * B_];
__device__ float g_hp  [NBLK * 1024];
__device__ int   g_cntA[T_ * 8];
__device__ int   g_cntB[T_ * 16];
__device__ int   g_done[T_];

__device__ __forceinline__ ull pack2(float a, float b) {
    ull d;
    unsigned x = __float_as_uint(a), y = __float_as_uint(b);
    asm("mov.b64 %0, {%1,%2};" : "=l"(d) : "r"(x), "r"(y));
    return d;
}
__device__ __forceinline__ ull dup2(float a) { return pack2(a, a); }
__device__ __forceinline__ void unpack2(ull s, float& a, float& b) {
    unsigned x, y;
    asm("mov.b64 {%0,%1}, %2;" : "=r"(x), "=r"(y) : "l"(s));
    a = __uint_as_float(x); b = __uint_as_float(y);
}
__device__ __forceinline__ ull fma2(ull a, ull b, ull c) {
    ull d;
    asm("fma.rn.f32x2 %0, %1, %2, %3;" : "=l"(d) : "l"(a), "l"(b), "l"(c));
    return d;
}
__device__ __forceinline__ float sigmoidf(float x) { return 1.0f / (1.0f + __expf(-x)); }

__device__ __forceinline__ int ld_acq(const int* p) {
    int v;
    asm volatile("ld.acquire.gpu.global.b32 %0, [%1];" : "=r"(v) : "l"(p) : "memory");
    return v;
}
__device__ __forceinline__ int atom_add_acqrel(int* p, int v) {
    int old;
    asm volatile("atom.acq_rel.gpu.global.add.s32 %0, [%1], %2;"
                 : "=r"(old) : "l"(p), "r"(v) : "memory");
    return old;
}
__device__ __forceinline__ void cp16(float* s, const float* g) {
    unsigned sa = (unsigned)__cvta_generic_to_shared(s);
    asm volatile("cp.async.cg.shared.global [%0], [%1], 16;" :: "r"(sa), "l"(g));
}
#define CP_COMMIT() asm volatile("cp.async.commit_group;")
#define CP_WAIT0()  asm volatile("cp.async.wait_group 0;")

// pure spin — NO __nanosleep (suspected coarse-granularity oversleep on chain)
#define SPIN_UNTIL(ptr, val) do { while (ld_acq(ptr) != (val)) { } } while (0)

// =====================================================================
// proj_in = x @ W_in^T (known-good). Block (0,0) also zeroes the
// dataflow counters for this launch/replay (scan runs after, same stream).
// =====================================================================
__global__ void __launch_bounds__(256) proj_in_kernel(const float* __restrict__ x,
                                                      const float* __restrict__ W_in) {
    __shared__ __align__(16) float As[16][128];
    __shared__ __align__(16) float Bs[16][128];
    const int tid = threadIdx.x;

    if (blockIdx.x == 0 && blockIdx.y == 0) {
        for (int i = tid; i < T_ * 8; i += 256)  g_cntA[i] = 0;
        for (int i = tid; i < T_ * 16; i += 256) g_cntB[i] = 0;
        for (int i = tid; i < T_; i += 256)      g_done[i] = 0;
        __threadfence();
    }

    const int m0 = blockIdx.y * 128;
    const int n0 = blockIdx.x * 128;
    const int tm = tid >> 4;
    const int tn = tid & 15;

    ull acc[8][4];
#pragma unroll
    for (int i = 0; i < 8; i++)
#pragma unroll
        for (int j = 0; j < 4; j++) acc[i][j] = 0ull;

    for (int kk = 0; kk < DIN_; kk += 16) {
#pragma unroll
        for (int r = 0; r < 2; r++) {
            int f = tid + r * 256;
            int row = f >> 2;
            int kq = f & 3;
            float4 va = *(const float4*)&x[(size_t)(m0 + row) * DIN_ + kk + kq * 4];
            As[kq * 4 + 0][row] = va.x; As[kq * 4 + 1][row] = va.y;
            As[kq * 4 + 2][row] = va.z; As[kq * 4 + 3][row] = va.w;
            float4 vb = *(const float4*)&W_in[(size_t)(n0 + row) * DIN_ + kk + kq * 4];
            Bs[kq * 4 + 0][row] = vb.x; Bs[kq * 4 + 1][row] = vb.y;
            Bs[kq * 4 + 2][row] = vb.z; Bs[kq * 4 + 3][row] = vb.w;
        }
        __syncthreads();
#pragma unroll
        for (int k = 0; k < 16; k++) {
            float4 a0 = *(const float4*)&As[k][tm * 8];
            float4 a1 = *(const float4*)&As[k][tm * 8 + 4];
            ulonglong2 b0 = *(const ulonglong2*)&Bs[k][tn * 8];
            ulonglong2 b1 = *(const ulonglong2*)&Bs[k][tn * 8 + 4];
            float av[8] = {a0.x, a0.y, a0.z, a0.w, a1.x, a1.y, a1.z, a1.w};
#pragma unroll
            for (int i = 0; i < 8; i++) {
                ull pa = dup2(av[i]);
                acc[i][0] = fma2(pa, b0.x, acc[i][0]);
                acc[i][1] = fma2(pa, b0.y, acc[i][1]);
                acc[i][2] = fma2(pa, b1.x, acc[i][2]);
                acc[i][3] = fma2(pa, b1.y, acc[i][3]);
            }
        }
        __syncthreads();
    }
#pragma unroll
    for (int i = 0; i < 8; i++) {
        float o[8];
        unpack2(acc[i][0], o[0], o[1]); unpack2(acc[i][1], o[2], o[3]);
        unpack2(acc[i][2], o[4], o[5]); unpack2(acc[i][3], o[6], o[7]);
        size_t base = (size_t)(m0 + tm * 8 + i) * G_ + n0 + tn * 8;
        *(float4*)&g_pi[base]     = make_float4(o[0], o[1], o[2], o[3]);
        *(float4*)&g_pi[base + 4] = make_float4(o[4], o[5], o[6], o[7]);
    }
}

// =====================================================================
// scan: R8 structure (block-synchronous double-buffered GEMM),
// spin-waits, reordered finalizer.
// smem floats:
//   [0,16384)      s_big : pst (A stage) / a2 (B stage) / B reduce
//   [16384,24704)  sW0
//   [24704,33024)  sW1
//   [33024,37248)  s_pi
//   [37248,37249)  s_flag
//   [37256,54664)  sWpB
// =====================================================================
#define SMEM_FLOATS 54664

__device__ __forceinline__ void ldg_chunkW(float2* wreg, const float* __restrict__ W_state,
                                           int bid, int tid, int ch) {
#pragma unroll
    for (int r = 0; r < 8; r++) {
        int e  = r * NT + tid;
        int j  = e >> 5;
        int kp = e & 31;
        int jg = (j & 3) * C_ + bid * 32 + (j >> 2);
        wreg[r] = __ldg((const float2*)&W_state[(size_t)jg * H_ + ch * 64 + kp * 2]);
    }
}
__device__ __forceinline__ void sts_chunkW(float* buf, const float2* wreg, int tid) {
#pragma unroll
    for (int r = 0; r < 8; r++) {
        int e  = r * NT + tid;
        int j  = e >> 5;
        int kp = e & 31;
        ((float2*)buf)[kp * 130 + j] = wreg[r];
    }
}

__global__ void __launch_bounds__(NT, 1) scan_kernel(
    const int*   __restrict__ prev_idx,
    const float* __restrict__ prev_w,
    const float* __restrict__ W_state,
    const float* __restrict__ b_state,
    const float* __restrict__ W_proj,
    float* __restrict__ out)
{
    extern __shared__ __align__(16) float sm[];
    float* s_big  = sm;
    float* sW0    = sm + 16384;
    float* sW1    = sm + 24704;
    float* s_pi   = sm + 33024;
    int*   s_flag = (int*)(sm + 37248);
    float* sWpB   = sm + 37256;

    const int tid = threadIdx.x;
    const int bid = blockIdx.x;
    const int w   = tid >> 5;
    const int b   = tid & 31;
    const int ht  = bid >> 3;
    const int ks  = bid & 7;
    const int ksA = bid >> 4;

    for (int r = 0; r < 32; r++) {
        int e  = r * NT + tid;
        int hl = e >> 9;
        int c  = e & 511;
        sWpB[c * 34 + hl] = __ldg(&W_proj[(size_t)(ht * 32 + hl) * C_ + ks * 512 + c]);
    }
    const int cA = bid * 32 + w * 2;
    float bst[2][4];
#pragma unroll
    for (int ci = 0; ci < 2; ci++)
#pragma unroll
        for (int g = 0; g < 4; g++)
            bst[ci][g] = __ldg(&b_state[g * C_ + cA + ci]);
    __syncthreads();

    for (int t = 0; t < T_; t++) {
        // ---- step-independent loads (issue before any wait) ----
        int idxA[P_]; float wA[P_];
#pragma unroll
        for (int p = 0; p < P_; p++) {
            idxA[p] = __ldg(&prev_idx[(b * T_ + t) * P_ + p]);
            wA[p]   = __ldg(&prev_w [(b * T_ + t) * P_ + p]);
        }
        float pmv[2][P_];
#pragma unroll
        for (int ci = 0; ci < 2; ci++)
#pragma unroll
            for (int p = 0; p < P_; p++)
                pmv[ci][p] = g_mem[((size_t)idxA[p] * C_ + cA + ci) * B_ + b];
#pragma unroll
        for (int r = 0; r < 8; r++) {
            int e  = r * NT + tid;
            int bb = e >> 7;
            int gg = (e >> 5) & 3;
            int cl = e & 31;
            s_pi[(gg * 32 + cl) * 33 + bb] =
                __ldg(&g_pi[((size_t)(bb * T_ + t)) * G_ + gg * C_ + bid * 32 + cl]);
        }
        __syncthreads();   // order s_pi staging before epilogue reads (t==0 path)

        ull acc[8];
#pragma unroll
        for (int i = 0; i < 8; i++) acc[i] = 0ull;

        if (t > 0) {
            float2 wreg[8];
            ldg_chunkW(wreg, W_state, bid, tid, 0);
            if (tid == 0) SPIN_UNTIL(&g_done[t - 1], 16);
            __syncthreads();
#pragma unroll
            for (int r = 0; r < 8; r++) {
                int e = r * NT + tid;
                cp16(s_big + e * 4, g_pst2 + e * 4);
            }
            CP_COMMIT();
            sts_chunkW(sW0, wreg, tid);
            CP_WAIT0();
            __syncthreads();

#pragma unroll 1
            for (int ch = 0; ch < 8; ch++) {
                float* buf  = (ch & 1) ? sW1 : sW0;
                float* nbuf = (ch & 1) ? sW0 : sW1;
                if (ch < 7) ldg_chunkW(wreg, W_state, bid, tid, ch + 1);
#pragma unroll
                for (int kp = 0; kp < 32; kp++) {
                    ull pa = *(const ull*)(s_big + ((ch * 32 + kp) * 64 + b * 2));
                    const ulonglong2* wp = (const ulonglong2*)(buf + (kp * 130 + w * 8) * 2);
                    ulonglong2 q0 = wp[0], q1 = wp[1], q2 = wp[2], q3 = wp[3];
                    acc[0] = fma2(q0.x, pa, acc[0]); acc[1] = fma2(q0.y, pa, acc[1]);
                    acc[2] = fma2(q1.x, pa, acc[2]); acc[3] = fma2(q1.y, pa, acc[3]);
                    acc[4] = fma2(q2.x, pa, acc[4]); acc[5] = fma2(q2.y, pa, acc[5]);
                    acc[6] = fma2(q3.x, pa, acc[6]); acc[7] = fma2(q3.y, pa, acc[7]);
                }
                __syncthreads();
                if (ch < 7) sts_chunkW(nbuf, wreg, tid);
                __syncthreads();
            }
        }

        // ---- A epilogue ----
        {
            float a2v[2];
#pragma unroll
            for (int ci = 0; ci < 2; ci++) {
                float pmem = 0.f;
#pragma unroll
                for (int p = 0; p < P_; p++) pmem += wA[p] * pmv[ci][p];
                float gv[4];
#pragma unroll
                for (int g = 0; g < 4; g++) {
                    float lo, hi;
                    unpack2(acc[ci * 4 + g], lo, hi);
                    gv[g] = lo + hi + s_pi[(g * 32 + w * 2 + ci) * 33 + b] + bst[ci][g];
                }
                float ig = sigmoidf(gv[0]);
                float fg = sigmoidf(gv[1]);
                float mi = tanhf(gv[2]);
                float og = sigmoidf(gv[3]);
                float mem = fminf(3.f, fmaxf(-3.f, ig * mi + fg * pmem));
                g_mem[((size_t)t * C_ + cA + ci) * B_ + b] = mem;
                a2v[ci] = og * tanhf(mem);
            }
            *(float2*)&g_a2[(bid * 16 + w) * 64 + b * 2] = make_float2(a2v[0], a2v[1]);
        }
        __syncthreads();
        if (tid == 0) atom_add_acqrel(&g_cntA[t * 8 + ksA], 1);

        // ================= Phase B =================
        if (tid == 0) SPIN_UNTIL(&g_cntA[t * 8 + ks], 16);
        __syncthreads();
#pragma unroll
        for (int r = 0; r < 8; r++) {
            int e = r * NT + tid;
            cp16(s_big + e * 4, g_a2 + ks * 16384 + e * 4);
        }
        CP_COMMIT();
        CP_WAIT0();
        __syncthreads();

        ull pac[8];
#pragma unroll
        for (int i = 0; i < 8; i++) pac[i] = 0ull;
        const int hhalf = w & 1;
        const int cch   = w >> 1;
#pragma unroll 4
        for (int cp = 0; cp < 32; cp++) {
            int cl2 = cch * 32 + cp;
            ull av = *(const ull*)(s_big + cl2 * 64 + b * 2);
            float alo, ahi;
            unpack2(av, alo, ahi);
            ull dlo = dup2(alo), dhi = dup2(ahi);
            int c0 = cl2 * 2;
#pragma unroll
            for (int hp = 0; hp < 8; hp++) {
                ull w0 = *(const ull*)(sWpB + c0 * 34 + (hhalf * 8 + hp) * 2);
                ull w1 = *(const ull*)(sWpB + (c0 + 1) * 34 + (hhalf * 8 + hp) * 2);
                pac[hp] = fma2(w0, dlo, pac[hp]);
                pac[hp] = fma2(w1, dhi, pac[hp]);
            }
        }
        __syncthreads();
#pragma unroll
        for (int hp = 0; hp < 8; hp++)
            *(ull*)(s_big + ((w * 8 + hp) * 64 + b * 2)) = pac[hp];
        __syncthreads();
#pragma unroll
        for (int r2 = 0; r2 < 2; r2++) {
            int o  = r2 * NT + tid;
            int hl = o >> 5, bb = o & 31;
            int ph   = hl >> 4;
            int hpin = (hl >> 1) & 7;
            int par  = hl & 1;
            float s = 0.f;
#pragma unroll
            for (int q = 0; q < 8; q++)
                s += s_big[((q * 2 + ph) * 8 + hpin) * 64 + bb * 2 + par];
            g_hp[bid * 1024 + hl * 32 + bb] = s;
        }
        __syncthreads();
        if (tid == 0) s_flag[0] = atom_add_acqrel(&g_cntB[t * 16 + ht], 1);
        __syncthreads();

        // ================= Phase C: finalize (release early, out after) =================
        if (s_flag[0] == 7) {
            // 1) issue all partial + gather loads with MLP
            float part[2];
            int   ipg[2][P_];
            float wvg[2][P_];
#pragma unroll
            for (int r2 = 0; r2 < 2; r2++) {
                int o  = r2 * NT + tid;
                int hl = o >> 5, bb = o & 31;
                float s = 0.f;
#pragma unroll
                for (int q = 0; q < 8; q++)
                    s += __ldcg(&g_hp[(ht * 8 + q) * 1024 + hl * 32 + bb]);
                part[r2] = s;
                if (t < T_ - 1) {
#pragma unroll
                    for (int p = 0; p < P_; p++) {
                        ipg[r2][p] = __ldg(&prev_idx[(bb * T_ + t + 1) * P_ + p]);
                        wvg[r2][p] = __ldg(&prev_w [(bb * T_ + t + 1) * P_ + p]);
                    }
                }
            }
            float sv[2];
#pragma unroll
            for (int r2 = 0; r2 < 2; r2++) {
                int o  = r2 * NT + tid;
                int hl = o >> 5, bb = o & 31;
                float s = fminf(3.f, fmaxf(-3.f, part[r2]));
                sv[r2] = s;
                const int hg = ht * 32 + hl;
                g_st[((size_t)t * H_ + hg) * B_ + bb] = s;
                if (t < T_ - 1) {
                    float pv = 0.f;
#pragma unroll
                    for (int p = 0; p < P_; p++) {
                        float v = (ipg[r2][p] == t)
                                  ? s
                                  : __ldcg(&g_st[((size_t)ipg[r2][p] * H_ + hg) * B_ + bb]);
                        pv += wvg[r2][p] * v;
                    }
                    g_pst2[(hg >> 1) * 64 + bb * 2 + (hg & 1)] = pv;
                }
            }
            __syncthreads();
            if (tid == 0) atom_add_acqrel(&g_done[t], 1);
            // out stores AFTER the release — off the dependency chain
#pragma unroll
            for (int r2 = 0; r2 < 2; r2++) {
                int o  = r2 * NT + tid;
                int hl = o >> 5, bb = o & 31;
                out[((size_t)bb * T_ + t) * H_ + ht * 32 + hl] = sv[r2];
            }
        }
        __syncthreads();
    }
}

extern "C" void kernel_launch(void* const* d_in, const int* in_sizes, int n_in,
                              void* d_out, int out_size) {
    const float* x        = (const float*)d_in[0];
    const int*   prev_idx = (const int*)  d_in[1];
    const float* prev_w   = (const float*)d_in[2];
    const float* W_in     = (const float*)d_in[3];
    const float* W_state  = (const float*)d_in[4];
    const float* b_state  = (const float*)d_in[5];
    const float* W_proj   = (const float*)d_in[6];
    float* out = (float*)d_out;
    (void)in_sizes; (void)n_in; (void)out_size;

    const int smem = SMEM_FLOATS * (int)sizeof(float);
    cudaFuncSetAttribute(scan_kernel, cudaFuncAttributeMaxDynamicSharedMemorySize, smem);

    proj_in_kernel<<<dim3(G_ / 128, (B_ * T_) / 128), 256>>>(x, W_in);
    scan_kernel<<<NBLK, NT, smem>>>(prev_idx, prev_w, W_state, b_state, W_proj, out);
}

// round 12
// speedup vs baseline: 1.5500x; 1.4837x over previous
#include <cuda_runtime.h>
#include <cuda_bf16.h>
#include <cstddef>
#include <cstdint>

#define B_   32
#define T_   128
#define P_   4
#define DIN_ 512
#define H_   512
#define C_   4096
#define G_   16384
#define NBLK 128
#define NT   512

typedef unsigned long long ull;

// ---------------- device scratch ----------------
__device__ float g_pi [(size_t)B_ * T_ * G_];
__device__ float g_mem[(size_t)T_ * C_ * B_];
__device__ float g_st [(size_t)T_ * H_ * B_];
__device__ float g_a2 [C_ * B_];
__device__ float g_hp [NBLK * 1024];
__device__ uint4 g_WAh[(size_t)NBLK * 32 * 8 * 32];   // W_state hi A-fragments (16 MB)
__device__ uint4 g_WAl[(size_t)NBLK * 32 * 8 * 32];   // W_state lo A-fragments (16 MB)
__device__ uint4 g_pBf[32 * 2 * 2 * 32];              // pst B-fragments [ks][ntp][s][lane]
__device__ int   g_cntA[T_ * 8];
__device__ int   g_cntB[T_ * 16];
__device__ int   g_done[T_];

// ---------------- f32x2 helpers ----------------
__device__ __forceinline__ ull pack2(float a, float b) {
    ull d; unsigned x = __float_as_uint(a), y = __float_as_uint(b);
    asm("mov.b64 %0, {%1,%2};" : "=l"(d) : "r"(x), "r"(y));
    return d;
}
__device__ __forceinline__ ull dup2(float a) { return pack2(a, a); }
__device__ __forceinline__ void unpack2(ull s, float& a, float& b) {
    unsigned x, y;
    asm("mov.b64 {%0,%1}, %2;" : "=r"(x), "=r"(y) : "l"(s));
    a = __uint_as_float(x); b = __uint_as_float(y);
}
__device__ __forceinline__ ull fma2(ull a, ull b, ull c) {
    ull d;
    asm("fma.rn.f32x2 %0, %1, %2, %3;" : "=l"(d) : "l"(a), "l"(b), "l"(c));
    return d;
}
__device__ __forceinline__ float sigmoidf(float x) { return 1.0f / (1.0f + __expf(-x)); }

// ---------------- HMMA m16n8k16 bf16 (plain sm_80+ PTX, no arch suffix) ----------------
__device__ __forceinline__ void mma_bf16(float* d, const uint4& a, uint32_t b0, uint32_t b1) {
    asm volatile(
        "mma.sync.aligned.m16n8k16.row.col.f32.bf16.bf16.f32 "
        "{%0,%1,%2,%3}, {%4,%5,%6,%7}, {%8,%9}, {%0,%1,%2,%3};"
        : "+f"(d[0]), "+f"(d[1]), "+f"(d[2]), "+f"(d[3])
        : "r"(a.x), "r"(a.y), "r"(a.z), "r"(a.w), "r"(b0), "r"(b1));
}

// ---------------- sync primitives ----------------
__device__ __forceinline__ int ld_acq(const int* p) {
    int v;
    asm volatile("ld.acquire.gpu.global.b32 %0, [%1];" : "=r"(v) : "l"(p) : "memory");
    return v;
}
__device__ __forceinline__ int atom_add_acqrel(int* p, int v) {
    int old;
    asm volatile("atom.acq_rel.gpu.global.add.s32 %0, [%1], %2;"
                 : "=r"(old) : "l"(p), "r"(v) : "memory");
    return old;
}
__device__ __forceinline__ void cp16(uint32_t saddr, const void* g) {
    asm volatile("cp.async.cg.shared.global [%0], [%1], 16;" :: "r"(saddr), "l"(g));
}
#define CP_COMMIT() asm volatile("cp.async.commit_group;")
#define CP_WAIT0()  asm volatile("cp.async.wait_group 0;")
#define SPIN_UNTIL(ptr, val) do { while (ld_acq(ptr) != (val)) { } } while (0)

// =====================================================================
// prep: pack W_state into per-lane bf16 hi/lo A-fragments.
// Fragment (m16n8k16 row-major A): a0={r,c0..c0+1} a1={r+8,..} a2={r,c0+8..} a3={r+8,c0+8..}
// with r = mt*16 + lane/4, c0 = ks*16 + (lane%4)*2.  j -> row (j>>5)*C + bid*32 + (j&31).
// =====================================================================
__device__ __forceinline__ uint32_t bfsplit(float2 v, float2& rem) {
    __nv_bfloat16 hx = __float2bfloat16(v.x);
    __nv_bfloat16 hy = __float2bfloat16(v.y);
    rem.x = v.x - __bfloat162float(hx);
    rem.y = v.y - __bfloat162float(hy);
    __nv_bfloat162 t; t.x = hx; t.y = hy;
    return *(uint32_t*)&t;
}
__device__ __forceinline__ uint32_t bfpack(float2 v) {
    __nv_bfloat162 t; t.x = __float2bfloat16(v.x); t.y = __float2bfloat16(v.y);
    return *(uint32_t*)&t;
}

__global__ void __launch_bounds__(256) wfrag_kernel(const float* __restrict__ W_state) {
    unsigned idx = blockIdx.x * 256 + threadIdx.x;    // < 128*8192
    int bid = idx >> 13;
    int rem = idx & 8191;
    int ks  = rem >> 8;
    int r2  = rem & 255;
    int mt  = r2 >> 5;
    int lane = r2 & 31;

    int r0 = mt * 16 + (lane >> 2);
    int r1 = r0 + 8;
    int c0 = ks * 16 + (lane & 3) * 2;
    size_t row0 = (size_t)((r0 >> 5) * C_ + bid * 32 + (r0 & 31)) * H_;
    size_t row1 = (size_t)((r1 >> 5) * C_ + bid * 32 + (r1 & 31)) * H_;

    float2 v00 = *(const float2*)&W_state[row0 + c0];
    float2 v10 = *(const float2*)&W_state[row1 + c0];
    float2 v01 = *(const float2*)&W_state[row0 + c0 + 8];
    float2 v11 = *(const float2*)&W_state[row1 + c0 + 8];

    float2 l00, l10, l01, l11;
    uint4 hi, lo;
    hi.x = bfsplit(v00, l00); hi.y = bfsplit(v10, l10);
    hi.z = bfsplit(v01, l01); hi.w = bfsplit(v11, l11);
    lo.x = bfpack(l00); lo.y = bfpack(l10); lo.z = bfpack(l01); lo.w = bfpack(l11);
    g_WAh[idx] = hi;
    g_WAl[idx] = lo;
}

// =====================================================================
// proj_in = x @ W_in^T (known-good). Block (0,0) zeroes dataflow counters.
// =====================================================================
__global__ void __launch_bounds__(256) proj_in_kernel(const float* __restrict__ x,
                                                      const float* __restrict__ W_in) {
    __shared__ __align__(16) float As[16][128];
    __shared__ __align__(16) float Bs[16][128];
    const int tid = threadIdx.x;

    if (blockIdx.x == 0 && blockIdx.y == 0) {
        for (int i = tid; i < T_ * 8; i += 256)  g_cntA[i] = 0;
        for (int i = tid; i < T_ * 16; i += 256) g_cntB[i] = 0;
        for (int i = tid; i < T_; i += 256)      g_done[i] = 0;
        __threadfence();
    }

    const int m0 = blockIdx.y * 128;
    const int n0 = blockIdx.x * 128;
    const int tm = tid >> 4;
    const int tn = tid & 15;

    ull acc[8][4];
#pragma unroll
    for (int i = 0; i < 8; i++)
#pragma unroll
        for (int j = 0; j < 4; j++) acc[i][j] = 0ull;

    for (int kk = 0; kk < DIN_; kk += 16) {
#pragma unroll
        for (int r = 0; r < 2; r++) {
            int f = tid + r * 256;
            int row = f >> 2;
            int kq = f & 3;
            float4 va = *(const float4*)&x[(size_t)(m0 + row) * DIN_ + kk + kq * 4];
            As[kq * 4 + 0][row] = va.x; As[kq * 4 + 1][row] = va.y;
            As[kq * 4 + 2][row] = va.z; As[kq * 4 + 3][row] = va.w;
            float4 vb = *(const float4*)&W_in[(size_t)(n0 + row) * DIN_ + kk + kq * 4];
            Bs[kq * 4 + 0][row] = vb.x; Bs[kq * 4 + 1][row] = vb.y;
            Bs[kq * 4 + 2][row] = vb.z; Bs[kq * 4 + 3][row] = vb.w;
        }
        __syncthreads();
#pragma unroll
        for (int k = 0; k < 16; k++) {
            float4 a0 = *(const float4*)&As[k][tm * 8];
            float4 a1 = *(const float4*)&As[k][tm * 8 + 4];
            ulonglong2 b0 = *(const ulonglong2*)&Bs[k][tn * 8];
            ulonglong2 b1 = *(const ulonglong2*)&Bs[k][tn * 8 + 4];
            float av[8] = {a0.x, a0.y, a0.z, a0.w, a1.x, a1.y, a1.z, a1.w};
#pragma unroll
            for (int i = 0; i < 8; i++) {
                ull pa = dup2(av[i]);
                acc[i][0] = fma2(pa, b0.x, acc[i][0]);
                acc[i][1] = fma2(pa, b0.y, acc[i][1]);
                acc[i][2] = fma2(pa, b1.x, acc[i][2]);
                acc[i][3] = fma2(pa, b1.y, acc[i][3]);
            }
        }
        __syncthreads();
    }
#pragma unroll
    for (int i = 0; i < 8; i++) {
        float o[8];
        unpack2(acc[i][0], o[0], o[1]); unpack2(acc[i][1], o[2], o[3]);
        unpack2(acc[i][2], o[4], o[5]); unpack2(acc[i][3], o[6], o[7]);
        size_t base = (size_t)(m0 + tm * 8 + i) * G_ + n0 + tn * 8;
        *(float4*)&g_pi[base]     = make_float4(o[0], o[1], o[2], o[3]);
        *(float4*)&g_pi[base + 4] = make_float4(o[4], o[5], o[6], o[7]);
    }
}

// =====================================================================
// scan: 128 blocks x 512 threads. Phase A = HMMA bf16 hi/lo.
// smem floats:
//   [0,16384)      sBig : phase-B a2 stage + reduce; sD (128 x 34) aliases front
//   [16384,20608)  s_pi : 128 x 33
//   [20608,36992)  sWpB : 512 c x 32 h
//   [36992]        s_flag
// =====================================================================
#define SBIG 0
#define SPI  16384
#define SWPB 20608
#define SFLG 36992
#define SMEM_FLOATS 36996

__global__ void __launch_bounds__(NT, 1) scan_kernel(
    const int*   __restrict__ prev_idx,
    const float* __restrict__ prev_w,
    const float* __restrict__ b_state,
    const float* __restrict__ W_proj,
    float* __restrict__ out)
{
    extern __shared__ __align__(16) float sm[];
    float* sBig  = sm + SBIG;
    float* sD    = sm + SBIG;            // alias (phase A output, consumed before B staging)
    float* s_pi  = sm + SPI;
    float* sWpB  = sm + SWPB;
    int*   s_flag = (int*)(sm + SFLG);
    const uint32_t smb = (uint32_t)__cvta_generic_to_shared(sm);

    const int tid = threadIdx.x;
    const int bid = blockIdx.x;
    const int w   = tid >> 5;
    const int b   = tid & 31;
    const int ht  = bid >> 3;
    const int ks  = bid & 7;
    const int ksA = bid >> 4;

    // persistent W_proj slice: sWpB[c*32 + hl]
    for (int r = 0; r < 32; r++) {
        int e  = r * NT + tid;
        int hl = e >> 9;
        int c  = e & 511;
        sWpB[c * 32 + hl] = __ldg(&W_proj[(size_t)(ht * 32 + hl) * C_ + ks * 512 + c]);
    }
    const int cA = bid * 32 + w * 2;
    float bst[2][4];
#pragma unroll
    for (int ci = 0; ci < 2; ci++)
#pragma unroll
        for (int g = 0; g < 4; g++)
            bst[ci][g] = __ldg(&b_state[g * C_ + cA + ci]);
    __syncthreads();

    const uint4* WAh = g_WAh + (size_t)bid * 8192;
    const uint4* WAl = g_WAl + (size_t)bid * 8192;
    const int mt  = w & 7;
    const int ntp = w >> 3;

    for (int t = 0; t < T_; t++) {
        // ---- step-independent loads ----
        int idxA[P_]; float wA[P_];
#pragma unroll
        for (int p = 0; p < P_; p++) {
            idxA[p] = __ldg(&prev_idx[(b * T_ + t) * P_ + p]);
            wA[p]   = __ldg(&prev_w [(b * T_ + t) * P_ + p]);
        }
        float pmv[2][P_];
#pragma unroll
        for (int ci = 0; ci < 2; ci++)
#pragma unroll
            for (int p = 0; p < P_; p++)
                pmv[ci][p] = g_mem[((size_t)idxA[p] * C_ + cA + ci) * B_ + b];
#pragma unroll
        for (int r = 0; r < 8; r++) {
            int e  = r * NT + tid;
            int bb = e >> 7;
            int gg = (e >> 5) & 3;
            int cl = e & 31;
            s_pi[(gg * 32 + cl) * 33 + bb] =
                __ldg(&g_pi[((size_t)(bb * T_ + t)) * G_ + gg * C_ + bid * 32 + cl]);
        }
        __syncthreads();   // order s_pi staging before epilogue reads (t==0 path)

        // ================= Phase A: HMMA GEMM (t>0) =================
        if (t > 0) {
            if (tid == 0) SPIN_UNTIL(&g_done[t - 1], 16);
            __syncthreads();

            float d0[4] = {0.f, 0.f, 0.f, 0.f};
            float d1[4] = {0.f, 0.f, 0.f, 0.f};
#pragma unroll 4
            for (int k2 = 0; k2 < 32; k2++) {
                uint4 Ah = __ldg(&WAh[(k2 * 8 + mt) * 32 + b]);
                uint4 Al = __ldg(&WAl[(k2 * 8 + mt) * 32 + b]);
                uint4 Bh = __ldcg(&g_pBf[((k2 * 2 + ntp) * 2 + 0) * 32 + b]);
                uint4 Bl = __ldcg(&g_pBf[((k2 * 2 + ntp) * 2 + 1) * 32 + b]);
                mma_bf16(d0, Ah, Bh.x, Bh.y);
                mma_bf16(d1, Ah, Bh.z, Bh.w);
                mma_bf16(d0, Ah, Bl.x, Bl.y);
                mma_bf16(d1, Ah, Bl.z, Bl.w);
                mma_bf16(d0, Al, Bh.x, Bh.y);
                mma_bf16(d1, Al, Bh.z, Bh.w);
            }
            // publish D[j][b] to sD (j = mt*16 + lane/4 (+8), b = ntp*16 + t2*8 + (lane%4)*2 (+1))
            {
                int j0 = mt * 16 + (b >> 2);
                int bc = ntp * 16 + (b & 3) * 2;
                *(float2*)&sD[j0 * 34 + bc]           = make_float2(d0[0], d0[1]);
                *(float2*)&sD[(j0 + 8) * 34 + bc]     = make_float2(d0[2], d0[3]);
                *(float2*)&sD[j0 * 34 + bc + 8]       = make_float2(d1[0], d1[1]);
                *(float2*)&sD[(j0 + 8) * 34 + bc + 8] = make_float2(d1[2], d1[3]);
            }
            __syncthreads();
        }

        // ---- A epilogue: gates + mem + a2 ----
        {
            float a2v[2];
#pragma unroll
            for (int ci = 0; ci < 2; ci++) {
                float pmem = 0.f;
#pragma unroll
                for (int p = 0; p < P_; p++) pmem += wA[p] * pmv[ci][p];
                float gv[4];
#pragma unroll
                for (int g = 0; g < 4; g++) {
                    float mmav = (t > 0) ? sD[(g * 32 + w * 2 + ci) * 34 + b] : 0.f;
                    gv[g] = mmav + s_pi[(g * 32 + w * 2 + ci) * 33 + b] + bst[ci][g];
                }
                float ig = sigmoidf(gv[0]);
                float fg = sigmoidf(gv[1]);
                float mi = tanhf(gv[2]);
                float og = sigmoidf(gv[3]);
                float mem = fminf(3.f, fmaxf(-3.f, ig * mi + fg * pmem));
                g_mem[((size_t)t * C_ + cA + ci) * B_ + b] = mem;
                a2v[ci] = og * tanhf(mem);
            }
            *(float2*)&g_a2[(bid * 16 + w) * 64 + b * 2] = make_float2(a2v[0], a2v[1]);
        }
        __syncthreads();
        if (tid == 0) atom_add_acqrel(&g_cntA[t * 8 + ksA], 1);

        // ================= Phase B =================
        if (tid == 0) SPIN_UNTIL(&g_cntA[t * 8 + ks], 16);
        __syncthreads();
#pragma unroll
        for (int r = 0; r < 8; r++) {
            int e = r * NT + tid;
            cp16(smb + SBIG * 4 + e * 16, (const char*)(g_a2 + ks * 16384) + e * 16);
        }
        CP_COMMIT();
        CP_WAIT0();
        __syncthreads();

        ull pac[8];
#pragma unroll
        for (int i = 0; i < 8; i++) pac[i] = 0ull;
        const int hhalf = w & 1;
        const int cch   = w >> 1;
#pragma unroll 4
        for (int cp = 0; cp < 32; cp++) {
            int cl2 = cch * 32 + cp;
            ull av = *(const ull*)(sBig + cl2 * 64 + b * 2);
            float alo, ahi;
            unpack2(av, alo, ahi);
            ull dlo = dup2(alo), dhi = dup2(ahi);
            int c0 = cl2 * 2;
            const float* w0p = sWpB + c0 * 32 + hhalf * 16;
            const float* w1p = w0p + 32;
#pragma unroll
            for (int q = 0; q < 4; q++) {
                ulonglong2 wa = ((const ulonglong2*)w0p)[q];
                ulonglong2 wb = ((const ulonglong2*)w1p)[q];
                pac[q * 2]     = fma2(wa.x, dlo, pac[q * 2]);
                pac[q * 2]     = fma2(wb.x, dhi, pac[q * 2]);
                pac[q * 2 + 1] = fma2(wa.y, dlo, pac[q * 2 + 1]);
                pac[q * 2 + 1] = fma2(wb.y, dhi, pac[q * 2 + 1]);
            }
        }
        __syncthreads();
#pragma unroll
        for (int hp = 0; hp < 8; hp++)
            *(ull*)(sBig + ((w * 8 + hp) * 64 + b * 2)) = pac[hp];
        __syncthreads();
#pragma unroll
        for (int r2 = 0; r2 < 2; r2++) {
            int o  = r2 * NT + tid;
            int hl = o >> 5, bb = o & 31;
            int ph   = hl >> 4;
            int hpin = (hl >> 1) & 7;
            int par  = hl & 1;
            float s = 0.f;
#pragma unroll
            for (int q = 0; q < 8; q++)
                s += sBig[((q * 2 + ph) * 8 + hpin) * 64 + bb * 2 + par];
            g_hp[bid * 1024 + hl * 32 + bb] = s;
        }
        __syncthreads();
        if (tid == 0) s_flag[0] = atom_add_acqrel(&g_cntB[t * 16 + ht], 1);
        __syncthreads();

        // ================= Phase C: finalize =================
        if (s_flag[0] == 7) {
            float part[2];
            int   ipg[2][P_];
            float wvg[2][P_];
#pragma unroll
            for (int r2 = 0; r2 < 2; r2++) {
                int o  = r2 * NT + tid;
                int hl = o >> 5, bb = o & 31;
                float s = 0.f;
#pragma unroll
                for (int q = 0; q < 8; q++)
                    s += __ldcg(&g_hp[(ht * 8 + q) * 1024 + hl * 32 + bb]);
                part[r2] = s;
                if (t < T_ - 1) {
#pragma unroll
                    for (int p = 0; p < P_; p++) {
                        ipg[r2][p] = __ldg(&prev_idx[(bb * T_ + t + 1) * P_ + p]);
                        wvg[r2][p] = __ldg(&prev_w [(bb * T_ + t + 1) * P_ + p]);
                    }
                }
            }
            float sv[2];
#pragma unroll
            for (int r2 = 0; r2 < 2; r2++) {
                int o  = r2 * NT + tid;
                int hl = o >> 5, bb = o & 31;
                float s = fminf(3.f, fmaxf(-3.f, part[r2]));
                sv[r2] = s;
                const int hg = ht * 32 + hl;
                g_st[((size_t)t * H_ + hg) * B_ + bb] = s;
                if (t < T_ - 1) {
                    float pv = 0.f;
#pragma unroll
                    for (int p = 0; p < P_; p++) {
                        float v = (ipg[r2][p] == t)
                                  ? s
                                  : __ldcg(&g_st[((size_t)ipg[r2][p] * H_ + hg) * B_ + bb]);
                        pv += wvg[r2][p] * v;
                    }
                    // write pst into B-fragment layout (bf16 hi/lo)
                    __nv_bfloat16 bh = __float2bfloat16(pv);
                    __nv_bfloat16 bl = __float2bfloat16(pv - __bfloat162float(bh));
                    int ksq  = hg >> 4;
                    int kin  = hg & 15;
                    int breg = kin >> 3;
                    int half = kin & 1;
                    int ntp2 = bb >> 4;
                    int ntl  = (bb >> 3) & 1;
                    int lane2 = (bb & 7) * 4 + ((kin & 7) >> 1);
                    char* basep = (char*)g_pBf;
                    size_t off = ((size_t)((ksq * 2 + ntp2) * 2) * 32 + lane2) * 16
                                 + (ntl * 2 + breg) * 4 + half * 2;
                    *(__nv_bfloat16*)(basep + off)        = bh;   // s=0 (hi)
                    *(__nv_bfloat16*)(basep + off + 512)  = bl;   // s=1 (+32 uint4)
                }
            }
            __syncthreads();
            if (tid == 0) atom_add_acqrel(&g_done[t], 1);
#pragma unroll
            for (int r2 = 0; r2 < 2; r2++) {
                int o  = r2 * NT + tid;
                int hl = o >> 5, bb = o & 31;
                out[((size_t)bb * T_ + t) * H_ + ht * 32 + hl] = sv[r2];
            }
        }
        __syncthreads();
    }
}

extern "C" void kernel_launch(void* const* d_in, const int* in_sizes, int n_in,
                              void* d_out, int out_size) {
    const float* x        = (const float*)d_in[0];
    const int*   prev_idx = (const int*)  d_in[1];
    const float* prev_w   = (const float*)d_in[2];
    const float* W_in     = (const float*)d_in[3];
    const float* W_state  = (const float*)d_in[4];
    const float* b_state  = (const float*)d_in[5];
    const float* W_proj   = (const float*)d_in[6];
    float* out = (float*)d_out;
    (void)in_sizes; (void)n_in; (void)out_size;

    const int smem = SMEM_FLOATS * (int)sizeof(float);
    cudaFuncSetAttribute(scan_kernel, cudaFuncAttributeMaxDynamicSharedMemorySize, smem);

    wfrag_kernel<<<(NBLK * 8192) / 256, 256>>>(W_state);
    proj_in_kernel<<<dim3(G_ / 128, (B_ * T_) / 128), 256>>>(x, W_in);
    scan_kernel<<<NBLK, NT, smem>>>(prev_idx, prev_w, b_state, W_proj, out);
}

// round 13
// speedup vs baseline: 1.6280x; 1.0503x over previous
#include <cuda_runtime.h>
#include <cuda_bf16.h>
#include <cstddef>
#include <cstdint>

#define B_   32
#define T_   128
#define P_   4
#define DIN_ 512
#define H_   512
#define C_   4096
#define G_   16384
#define NBLK 128
#define NT   512

typedef unsigned long long ull;

// ---------------- device scratch ----------------
__device__ float g_pi [(size_t)B_ * T_ * G_];
__device__ float g_mem[(size_t)T_ * B_ * C_];          // [t][b][c]  (NOTE layout)
__device__ float g_st [(size_t)T_ * H_ * B_];
__device__ float g_a2 [C_ * B_];
__device__ float g_hp [NBLK * 1024];
__device__ uint4 g_WAh[(size_t)NBLK * 32 * 8 * 32];    // W_state hi A-fragments
__device__ uint4 g_WAl[(size_t)NBLK * 32 * 8 * 32];    // W_state lo A-fragments
__device__ uint4 g_pBf[(size_t)T_ * 4096];             // per-step pst B-fragments (8 MB)
__device__ int   g_cntA[T_ * 8];
__device__ int   g_cntB[T_ * 16];
__device__ int   g_done[T_];

// ---------------- f32x2 helpers ----------------
__device__ __forceinline__ ull pack2(float a, float b) {
    ull d; unsigned x = __float_as_uint(a), y = __float_as_uint(b);
    asm("mov.b64 %0, {%1,%2};" : "=l"(d) : "r"(x), "r"(y));
    return d;
}
__device__ __forceinline__ ull dup2(float a) { return pack2(a, a); }
__device__ __forceinline__ void unpack2(ull s, float& a, float& b) {
    unsigned x, y;
    asm("mov.b64 {%0,%1}, %2;" : "=r"(x), "=r"(y) : "l"(s));
    a = __uint_as_float(x); b = __uint_as_float(y);
}
__device__ __forceinline__ ull fma2(ull a, ull b, ull c) {
    ull d;
    asm("fma.rn.f32x2 %0, %1, %2, %3;" : "=l"(d) : "l"(a), "l"(b), "l"(c));
    return d;
}
__device__ __forceinline__ float sigmoidf(float x) { return 1.0f / (1.0f + __expf(-x)); }

// ---------------- HMMA m16n8k16 bf16 ----------------
__device__ __forceinline__ void mma_bf16(float* d, const uint4& a, uint32_t b0, uint32_t b1) {
    asm volatile(
        "mma.sync.aligned.m16n8k16.row.col.f32.bf16.bf16.f32 "
        "{%0,%1,%2,%3}, {%4,%5,%6,%7}, {%8,%9}, {%0,%1,%2,%3};"
        : "+f"(d[0]), "+f"(d[1]), "+f"(d[2]), "+f"(d[3])
        : "r"(a.x), "r"(a.y), "r"(a.z), "r"(a.w), "r"(b0), "r"(b1));
}

// ---------------- sync primitives ----------------
__device__ __forceinline__ int ld_acq(const int* p) {
    int v;
    asm volatile("ld.acquire.gpu.global.b32 %0, [%1];" : "=r"(v) : "l"(p) : "memory");
    return v;
}
__device__ __forceinline__ int atom_add_acqrel(int* p, int v) {
    int old;
    asm volatile("atom.acq_rel.gpu.global.add.s32 %0, [%1], %2;"
                 : "=r"(old) : "l"(p), "r"(v) : "memory");
    return old;
}
__device__ __forceinline__ void cp16(uint32_t saddr, const void* g) {
    asm volatile("cp.async.cg.shared.global [%0], [%1], 16;" :: "r"(saddr), "l"(g));
}
#define CP_COMMIT() asm volatile("cp.async.commit_group;")
#define CP_WAIT0()  asm volatile("cp.async.wait_group 0;")
#define SPIN_UNTIL(ptr, val) do { while (ld_acq(ptr) != (val)) { } } while (0)

// =====================================================================
// prep: W_state -> bf16 hi/lo A-fragments (verified in R12)
// =====================================================================
__device__ __forceinline__ uint32_t bfsplit(float2 v, float2& rem) {
    __nv_bfloat16 hx = __float2bfloat16(v.x);
    __nv_bfloat16 hy = __float2bfloat16(v.y);
    rem.x = v.x - __bfloat162float(hx);
    rem.y = v.y - __bfloat162float(hy);
    __nv_bfloat162 t; t.x = hx; t.y = hy;
    return *(uint32_t*)&t;
}
__device__ __forceinline__ uint32_t bfpack(float2 v) {
    __nv_bfloat162 t; t.x = __float2bfloat16(v.x); t.y = __float2bfloat16(v.y);
    return *(uint32_t*)&t;
}

__global__ void __launch_bounds__(256) wfrag_kernel(const float* __restrict__ W_state) {
    unsigned idx = blockIdx.x * 256 + threadIdx.x;    // < 128*8192
    int bid = idx >> 13;
    int rem = idx & 8191;
    int ks  = rem >> 8;
    int r2  = rem & 255;
    int mt  = r2 >> 5;
    int lane = r2 & 31;

    int r0 = mt * 16 + (lane >> 2);
    int r1 = r0 + 8;
    int c0 = ks * 16 + (lane & 3) * 2;
    size_t row0 = (size_t)((r0 >> 5) * C_ + bid * 32 + (r0 & 31)) * H_;
    size_t row1 = (size_t)((r1 >> 5) * C_ + bid * 32 + (r1 & 31)) * H_;

    float2 v00 = *(const float2*)&W_state[row0 + c0];
    float2 v10 = *(const float2*)&W_state[row1 + c0];
    float2 v01 = *(const float2*)&W_state[row0 + c0 + 8];
    float2 v11 = *(const float2*)&W_state[row1 + c0 + 8];

    float2 l00, l10, l01, l11;
    uint4 hi, lo;
    hi.x = bfsplit(v00, l00); hi.y = bfsplit(v10, l10);
    hi.z = bfsplit(v01, l01); hi.w = bfsplit(v11, l11);
    lo.x = bfpack(l00); lo.y = bfpack(l10); lo.z = bfpack(l01); lo.w = bfpack(l11);
    g_WAh[idx] = hi;
    g_WAl[idx] = lo;
}

// =====================================================================
// proj_in = x @ W_in^T (known-good). Block (0,0) zeroes dataflow counters.
// =====================================================================
__global__ void __launch_bounds__(256) proj_in_kernel(const float* __restrict__ x,
                                                      const float* __restrict__ W_in) {
    __shared__ __align__(16) float As[16][128];
    __shared__ __align__(16) float Bs[16][128];
    const int tid = threadIdx.x;

    if (blockIdx.x == 0 && blockIdx.y == 0) {
        for (int i = tid; i < T_ * 8; i += 256)  g_cntA[i] = 0;
        for (int i = tid; i < T_ * 16; i += 256) g_cntB[i] = 0;
        for (int i = tid; i < T_; i += 256)      g_done[i] = 0;
        __threadfence();
    }

    const int m0 = blockIdx.y * 128;
    const int n0 = blockIdx.x * 128;
    const int tm = tid >> 4;
    const int tn = tid & 15;

    ull acc[8][4];
#pragma unroll
    for (int i = 0; i < 8; i++)
#pragma unroll
        for (int j = 0; j < 4; j++) acc[i][j] = 0ull;

    for (int kk = 0; kk < DIN_; kk += 16) {
#pragma unroll
        for (int r = 0; r < 2; r++) {
            int f = tid + r * 256;
            int row = f >> 2;
            int kq = f & 3;
            float4 va = *(const float4*)&x[(size_t)(m0 + row) * DIN_ + kk + kq * 4];
            As[kq * 4 + 0][row] = va.x; As[kq * 4 + 1][row] = va.y;
            As[kq * 4 + 2][row] = va.z; As[kq * 4 + 3][row] = va.w;
            float4 vb = *(const float4*)&W_in[(size_t)(n0 + row) * DIN_ + kk + kq * 4];
            Bs[kq * 4 + 0][row] = vb.x; Bs[kq * 4 + 1][row] = vb.y;
            Bs[kq * 4 + 2][row] = vb.z; Bs[kq * 4 + 3][row] = vb.w;
        }
        __syncthreads();
#pragma unroll
        for (int k = 0; k < 16; k++) {
            float4 a0 = *(const float4*)&As[k][tm * 8];
            float4 a1 = *(const float4*)&As[k][tm * 8 + 4];
            ulonglong2 b0 = *(const ulonglong2*)&Bs[k][tn * 8];
            ulonglong2 b1 = *(const ulonglong2*)&Bs[k][tn * 8 + 4];
            float av[8] = {a0.x, a0.y, a0.z, a0.w, a1.x, a1.y, a1.z, a1.w};
#pragma unroll
            for (int i = 0; i < 8; i++) {
                ull pa = dup2(av[i]);
                acc[i][0] = fma2(pa, b0.x, acc[i][0]);
                acc[i][1] = fma2(pa, b0.y, acc[i][1]);
                acc[i][2] = fma2(pa, b1.x, acc[i][2]);
                acc[i][3] = fma2(pa, b1.y, acc[i][3]);
            }
        }
        __syncthreads();
    }
#pragma unroll
    for (int i = 0; i < 8; i++) {
        float o[8];
        unpack2(acc[i][0], o[0], o[1]); unpack2(acc[i][1], o[2], o[3]);
        unpack2(acc[i][2], o[4], o[5]); unpack2(acc[i][3], o[6], o[7]);
        size_t base = (size_t)(m0 + tm * 8 + i) * G_ + n0 + tn * 8;
        *(float4*)&g_pi[base]     = make_float4(o[0], o[1], o[2], o[3]);
        *(float4*)&g_pi[base + 4] = make_float4(o[4], o[5], o[6], o[7]);
    }
}

// =====================================================================
// scan: 128 blocks x 512 threads. Phase A = HMMA; epilogue lane->c remap.
// smem floats: [0,16384) sBig (B stage / reduce; sD 128x34 aliases front)
//              [16384,32768) sWpB ; [32768] flag
// =====================================================================
#define SBIG 0
#define SWPB 16384
#define SFLG 32768
#define SMEM_FLOATS 32772

__global__ void __launch_bounds__(NT, 1) scan_kernel(
    const int*   __restrict__ prev_idx,
    const float* __restrict__ prev_w,
    const float* __restrict__ b_state,
    const float* __restrict__ W_proj,
    float* __restrict__ out)
{
    extern __shared__ __align__(16) float sm[];
    float* sBig  = sm + SBIG;
    float* sD    = sm + SBIG;
    float* sWpB  = sm + SWPB;
    int*   s_flag = (int*)(sm + SFLG);
    const uint32_t smb = (uint32_t)__cvta_generic_to_shared(sm);

    const int tid = threadIdx.x;
    const int bid = blockIdx.x;
    const int w   = tid >> 5;
    const int b   = tid & 31;          // lane
    const int ht  = bid >> 3;
    const int ks  = bid & 7;
    const int ksA = bid >> 4;

    // epilogue mapping: batch bE, c-pair index ll
    const int bE  = 2 * w + (b >> 4);
    const int ll  = b & 15;
    const int cE0 = bid * 32 + ll * 2;

    // persistent W_proj slice: sWpB[c*32 + hl]
    for (int r = 0; r < 32; r++) {
        int e  = r * NT + tid;
        int hl = e >> 9;
        int c  = e & 511;
        sWpB[c * 32 + hl] = __ldg(&W_proj[(size_t)(ht * 32 + hl) * C_ + ks * 512 + c]);
    }
    float bst[2][4];
#pragma unroll
    for (int ci = 0; ci < 2; ci++)
#pragma unroll
        for (int g = 0; g < 4; g++)
            bst[ci][g] = __ldg(&b_state[g * C_ + cE0 + ci]);
    __syncthreads();

    const uint4* WAh = g_WAh + (size_t)bid * 8192;
    const uint4* WAl = g_WAl + (size_t)bid * 8192;
    const int mt  = w & 7;
    const int ntp = w >> 3;

    for (int t = 0; t < T_; t++) {
        // ---- step-independent loads (coalesced; issued before any wait) ----
        float wAv[P_];
        float2 pm2[P_];
#pragma unroll
        for (int p = 0; p < P_; p++) {
            int ip = __ldg(&prev_idx[(bE * T_ + t) * P_ + p]);
            wAv[p] = __ldg(&prev_w [(bE * T_ + t) * P_ + p]);
            pm2[p] = *(const float2*)&g_mem[((size_t)ip * B_ + bE) * C_ + cE0];
        }
        float2 pi2[4];
#pragma unroll
        for (int g = 0; g < 4; g++)
            pi2[g] = __ldg((const float2*)&g_pi[(size_t)(bE * T_ + t) * G_ + g * C_ + cE0]);

        // ================= Phase A: HMMA GEMM (t>0) =================
        if (t > 0) {
            if (tid == 0) SPIN_UNTIL(&g_done[t - 1], 16);
            __syncthreads();

            const uint4* pBf = g_pBf + (size_t)t * 4096;   // per-step slice: __ldg safe
            float d0[4] = {0.f, 0.f, 0.f, 0.f};
            float d1[4] = {0.f, 0.f, 0.f, 0.f};
#pragma unroll 4
            for (int k2 = 0; k2 < 32; k2++) {
                uint4 Ah = __ldg(&WAh[(k2 * 8 + mt) * 32 + b]);
                uint4 Al = __ldg(&WAl[(k2 * 8 + mt) * 32 + b]);
                uint4 Bh = __ldg(&pBf[((k2 * 2 + ntp) * 2 + 0) * 32 + b]);
                uint4 Bl = __ldg(&pBf[((k2 * 2 + ntp) * 2 + 1) * 32 + b]);
                mma_bf16(d0, Ah, Bh.x, Bh.y);
                mma_bf16(d1, Ah, Bh.z, Bh.w);
                mma_bf16(d0, Ah, Bl.x, Bl.y);
                mma_bf16(d1, Ah, Bl.z, Bl.w);
                mma_bf16(d0, Al, Bh.x, Bh.y);
                mma_bf16(d1, Al, Bh.z, Bh.w);
            }
            {
                int j0 = mt * 16 + (b >> 2);
                int bc = ntp * 16 + (b & 3) * 2;
                *(float2*)&sD[j0 * 34 + bc]           = make_float2(d0[0], d0[1]);
                *(float2*)&sD[(j0 + 8) * 34 + bc]     = make_float2(d0[2], d0[3]);
                *(float2*)&sD[j0 * 34 + bc + 8]       = make_float2(d1[0], d1[1]);
                *(float2*)&sD[(j0 + 8) * 34 + bc + 8] = make_float2(d1[2], d1[3]);
            }
            __syncthreads();
        }

        // ---- A epilogue (lane->c): gates + mem + a2, all coalesced ----
        {
            float a2v[2], memv[2];
#pragma unroll
            for (int ci = 0; ci < 2; ci++) {
                float pmem = 0.f;
#pragma unroll
                for (int p = 0; p < P_; p++)
                    pmem += wAv[p] * ((ci == 0) ? pm2[p].x : pm2[p].y);
                float gv[4];
#pragma unroll
                for (int g = 0; g < 4; g++) {
                    float mmav = (t > 0) ? sD[(g * 32 + ll * 2 + ci) * 34 + bE] : 0.f;
                    float piv  = (ci == 0) ? pi2[g].x : pi2[g].y;
                    gv[g] = mmav + piv + bst[ci][g];
                }
                float ig = sigmoidf(gv[0]);
                float fg = sigmoidf(gv[1]);
                float mi = tanhf(gv[2]);
                float og = sigmoidf(gv[3]);
                memv[ci] = fminf(3.f, fmaxf(-3.f, ig * mi + fg * pmem));
                a2v[ci]  = og * tanhf(memv[ci]);
            }
            *(float2*)&g_mem[((size_t)t * B_ + bE) * C_ + cE0] = make_float2(memv[0], memv[1]);
            *(float2*)&g_a2[((size_t)bid * 16 + ll) * 64 + bE * 2] = make_float2(a2v[0], a2v[1]);
        }
        __syncthreads();
        if (tid == 0) atom_add_acqrel(&g_cntA[t * 8 + ksA], 1);

        // ================= Phase B =================
        if (tid == 0) SPIN_UNTIL(&g_cntA[t * 8 + ks], 16);
        __syncthreads();
#pragma unroll
        for (int r = 0; r < 8; r++) {
            int e = r * NT + tid;
            cp16(smb + SBIG * 4 + e * 16, (const char*)(g_a2 + ks * 16384) + e * 16);
        }
        CP_COMMIT();
        CP_WAIT0();
        __syncthreads();

        ull pac[8];
#pragma unroll
        for (int i = 0; i < 8; i++) pac[i] = 0ull;
        const int hhalf = w & 1;
        const int cch   = w >> 1;
#pragma unroll 4
        for (int cp = 0; cp < 32; cp++) {
            int cl2 = cch * 32 + cp;
            ull av = *(const ull*)(sBig + cl2 * 64 + b * 2);
            float alo, ahi;
            unpack2(av, alo, ahi);
            ull dlo = dup2(alo), dhi = dup2(ahi);
            int c0 = cl2 * 2;
            const float* w0p = sWpB + c0 * 32 + hhalf * 16;
            const float* w1p = w0p + 32;
#pragma unroll
            for (int q = 0; q < 4; q++) {
                ulonglong2 wa = ((const ulonglong2*)w0p)[q];
                ulonglong2 wb = ((const ulonglong2*)w1p)[q];
                pac[q * 2]     = fma2(wa.x, dlo, pac[q * 2]);
                pac[q * 2]     = fma2(wb.x, dhi, pac[q * 2]);
                pac[q * 2 + 1] = fma2(wa.y, dlo, pac[q * 2 + 1]);
                pac[q * 2 + 1] = fma2(wb.y, dhi, pac[q * 2 + 1]);
            }
        }
        __syncthreads();
#pragma unroll
        for (int hp = 0; hp < 8; hp++)
            *(ull*)(sBig + ((w * 8 + hp) * 64 + b * 2)) = pac[hp];
        __syncthreads();
#pragma unroll
        for (int r2 = 0; r2 < 2; r2++) {
            int o  = r2 * NT + tid;
            int hl = o >> 5, bb = o & 31;
            int ph   = hl >> 4;
            int hpin = (hl >> 1) & 7;
            int par  = hl & 1;
            float s = 0.f;
#pragma unroll
            for (int q = 0; q < 8; q++)
                s += sBig[((q * 2 + ph) * 8 + hpin) * 64 + bb * 2 + par];
            g_hp[bid * 1024 + hl * 32 + bb] = s;
        }
        __syncthreads();
        if (tid == 0) s_flag[0] = atom_add_acqrel(&g_cntB[t * 16 + ht], 1);
        __syncthreads();

        // ================= Phase C: finalize =================
        if (s_flag[0] == 7) {
            float part[2];
            int   ipg[2][P_];
            float wvg[2][P_];
#pragma unroll
            for (int r2 = 0; r2 < 2; r2++) {
                int o  = r2 * NT + tid;
                int hl = o >> 5, bb = o & 31;
                float s = 0.f;
#pragma unroll
                for (int q = 0; q < 8; q++)
                    s += __ldcg(&g_hp[(ht * 8 + q) * 1024 + hl * 32 + bb]);
                part[r2] = s;
                if (t < T_ - 1) {
#pragma unroll
                    for (int p = 0; p < P_; p++) {
                        ipg[r2][p] = __ldg(&prev_idx[(bb * T_ + t + 1) * P_ + p]);
                        wvg[r2][p] = __ldg(&prev_w [(bb * T_ + t + 1) * P_ + p]);
                    }
                }
            }
            float sv[2];
#pragma unroll
            for (int r2 = 0; r2 < 2; r2++) {
                int o  = r2 * NT + tid;
                int hl = o >> 5, bb = o & 31;
                float s = fminf(3.f, fmaxf(-3.f, part[r2]));
                sv[r2] = s;
                const int hg = ht * 32 + hl;
                g_st[((size_t)t * H_ + hg) * B_ + bb] = s;
                if (t < T_ - 1) {
                    float pv = 0.f;
#pragma unroll
                    for (int p = 0; p < P_; p++) {
                        float v = (ipg[r2][p] == t)
                                  ? s
                                  : __ldcg(&g_st[((size_t)ipg[r2][p] * H_ + hg) * B_ + bb]);
                        pv += wvg[r2][p] * v;
                    }
                    // write pst into NEXT step's B-fragment slice (bf16 hi/lo)
                    __nv_bfloat16 bh = __float2bfloat16(pv);
                    __nv_bfloat16 bl = __float2bfloat16(pv - __bfloat162float(bh));
                    int ksq  = hg >> 4;
                    int kin  = hg & 15;
                    int breg = kin >> 3;
                    int half = kin & 1;
                    int ntp2 = bb >> 4;
                    int ntl  = (bb >> 3) & 1;
                    int lane2 = (bb & 7) * 4 + ((kin & 7) >> 1);
                    char* basep = (char*)(g_pBf + (size_t)(t + 1) * 4096);
                    size_t off = ((size_t)((ksq * 2 + ntp2) * 2) * 32 + lane2) * 16
                                 + (ntl * 2 + breg) * 4 + half * 2;
                    *(__nv_bfloat16*)(basep + off)       = bh;   // s=0 (hi)
                    *(__nv_bfloat16*)(basep + off + 512) = bl;   // s=1 (+32 uint4)
                }
            }
            __syncthreads();
            if (tid == 0) atom_add_acqrel(&g_done[t], 1);
#pragma unroll
            for (int r2 = 0; r2 < 2; r2++) {
                int o  = r2 * NT + tid;
                int hl = o >> 5, bb = o & 31;
                out[((size_t)bb * T_ + t) * H_ + ht * 32 + hl] = sv[r2];
            }
        }
        __syncthreads();
    }
}

extern "C" void kernel_launch(void* const* d_in, const int* in_sizes, int n_in,
                              void* d_out, int out_size) {
    const float* x        = (const float*)d_in[0];
    const int*   prev_idx = (const int*)  d_in[1];
    const float* prev_w   = (const float*)d_in[2];
    const float* W_in     = (const float*)d_in[3];
    const float* W_state  = (const float*)d_in[4];
    const float* b_state  = (const float*)d_in[5];
    const float* W_proj   = (const float*)d_in[6];
    float* out = (float*)d_out;
    (void)in_sizes; (void)n_in; (void)out_size;

    const int smem = SMEM_FLOATS * (int)sizeof(float);
    cudaFuncSetAttribute(scan_kernel, cudaFuncAttributeMaxDynamicSharedMemorySize, smem);

    wfrag_kernel<<<(NBLK * 8192) / 256, 256>>>(W_state);
    proj_in_kernel<<<dim3(G_ / 128, (B_ * T_) / 128), 256>>>(x, W_in);
    scan_kernel<<<NBLK, NT, smem>>>(prev_idx, prev_w, b_state, W_proj, out);
}

// round 14
// speedup vs baseline: 2.0425x; 1.2546x over previous
#include <cuda_runtime.h>
#include <cuda_bf16.h>
#include <cstddef>
#include <cstdint>

#define B_   32
#define T_   128
#define P_   4
#define DIN_ 512
#define H_   512
#define C_   4096
#define G_   16384
#define NBLK 128
#define NT   512

typedef unsigned long long ull;

// ---------------- device scratch ----------------
__device__ float g_pi [(size_t)B_ * T_ * G_];
__device__ float g_mem[(size_t)T_ * B_ * C_];          // [t][b][c]
__device__ float g_st [(size_t)T_ * H_ * B_];
__device__ float g_a2 [C_ * B_];
__device__ float g_hp [NBLK * 1024];
__device__ uint4 g_WAh[(size_t)NBLK * 32 * 8 * 32];    // W_state hi A-frags (scan)
__device__ uint4 g_WAl[(size_t)NBLK * 32 * 8 * 32];    // W_state lo A-frags (scan)
__device__ uint4 g_pBf[(size_t)T_ * 4096];             // per-step pst B-frags (scan)
__device__ uint4 g_xfH[256 * 32 * 32];                 // x hi A-frags [mtile][k2][lane] (4 MB)
__device__ uint4 g_xfL[256 * 32 * 32];                 // x lo A-frags
__device__ uint4 g_wfH[1024 * 32 * 32];                // W_in hi B-frags [npair][k2][lane] (16 MB)
__device__ uint4 g_wfL[1024 * 32 * 32];                // W_in lo B-frags
__device__ int   g_cntA[T_ * 8];
__device__ int   g_cntB[T_ * 16];
__device__ int   g_done[T_];

// ---------------- f32x2 helpers ----------------
__device__ __forceinline__ ull pack2(float a, float b) {
    ull d; unsigned x = __float_as_uint(a), y = __float_as_uint(b);
    asm("mov.b64 %0, {%1,%2};" : "=l"(d) : "r"(x), "r"(y));
    return d;
}
__device__ __forceinline__ ull dup2(float a) { return pack2(a, a); }
__device__ __forceinline__ void unpack2(ull s, float& a, float& b) {
    unsigned x, y;
    asm("mov.b64 {%0,%1}, %2;" : "=r"(x), "=r"(y) : "l"(s));
    a = __uint_as_float(x); b = __uint_as_float(y);
}
__device__ __forceinline__ ull fma2(ull a, ull b, ull c) {
    ull d;
    asm("fma.rn.f32x2 %0, %1, %2, %3;" : "=l"(d) : "l"(a), "l"(b), "l"(c));
    return d;
}
__device__ __forceinline__ float sigmoidf(float x) { return 1.0f / (1.0f + __expf(-x)); }

// ---------------- HMMA m16n8k16 bf16 ----------------
__device__ __forceinline__ void mma_bf16(float* d, const uint4& a, uint32_t b0, uint32_t b1) {
    asm volatile(
        "mma.sync.aligned.m16n8k16.row.col.f32.bf16.bf16.f32 "
        "{%0,%1,%2,%3}, {%4,%5,%6,%7}, {%8,%9}, {%0,%1,%2,%3};"
        : "+f"(d[0]), "+f"(d[1]), "+f"(d[2]), "+f"(d[3])
        : "r"(a.x), "r"(a.y), "r"(a.z), "r"(a.w), "r"(b0), "r"(b1));
}

// ---------------- sync primitives ----------------
__device__ __forceinline__ int ld_acq(const int* p) {
    int v;
    asm volatile("ld.acquire.gpu.global.b32 %0, [%1];" : "=r"(v) : "l"(p) : "memory");
    return v;
}
__device__ __forceinline__ int atom_add_acqrel(int* p, int v) {
    int old;
    asm volatile("atom.acq_rel.gpu.global.add.s32 %0, [%1], %2;"
                 : "=r"(old) : "l"(p), "r"(v) : "memory");
    return old;
}
__device__ __forceinline__ void cp16(uint32_t saddr, const void* g) {
    asm volatile("cp.async.cg.shared.global [%0], [%1], 16;" :: "r"(saddr), "l"(g));
}
#define CP_COMMIT() asm volatile("cp.async.commit_group;")
#define CP_WAIT0()  asm volatile("cp.async.wait_group 0;")
#define SPIN_UNTIL(ptr, val) do { while (ld_acq(ptr) != (val)) { } } while (0)

// ---------------- bf16 split helpers ----------------
__device__ __forceinline__ uint32_t bfsplit(float2 v, float2& rem) {
    __nv_bfloat16 hx = __float2bfloat16(v.x);
    __nv_bfloat16 hy = __float2bfloat16(v.y);
    rem.x = v.x - __bfloat162float(hx);
    rem.y = v.y - __bfloat162float(hy);
    __nv_bfloat162 t; t.x = hx; t.y = hy;
    return *(uint32_t*)&t;
}
__device__ __forceinline__ uint32_t bfpack(float2 v) {
    __nv_bfloat162 t; t.x = __float2bfloat16(v.x); t.y = __float2bfloat16(v.y);
    return *(uint32_t*)&t;
}

// =====================================================================
// prep A-fragments from a row-major [rows][512] f32 matrix.
// A-frag (m16k16): a0={r,c0,c0+1} a1={r+8,·} a2={r,c0+8,·} a3={r+8,c0+8,·}
// out layout: frag[(mtile*32 + k2)*32 + lane]
// =====================================================================
__device__ __forceinline__ void make_afrag(const float* __restrict__ M, size_t row0, size_t row1,
                                           int c0, uint4& hi, uint4& lo) {
    float2 v00 = *(const float2*)&M[row0 + c0];
    float2 v10 = *(const float2*)&M[row1 + c0];
    float2 v01 = *(const float2*)&M[row0 + c0 + 8];
    float2 v11 = *(const float2*)&M[row1 + c0 + 8];
    float2 l00, l10, l01, l11;
    hi.x = bfsplit(v00, l00); hi.y = bfsplit(v10, l10);
    hi.z = bfsplit(v01, l01); hi.w = bfsplit(v11, l11);
    lo.x = bfpack(l00); lo.y = bfpack(l10); lo.z = bfpack(l01); lo.w = bfpack(l11);
}

// W_state scan A-frags (verified R12)
__global__ void __launch_bounds__(256) wfrag_kernel(const float* __restrict__ W_state) {
    unsigned idx = blockIdx.x * 256 + threadIdx.x;    // < 128*8192
    int bid = idx >> 13;
    int rem = idx & 8191;
    int ks  = rem >> 8;
    int r2  = rem & 255;
    int mt  = r2 >> 5;
    int lane = r2 & 31;
    int r0 = mt * 16 + (lane >> 2);
    int r1 = r0 + 8;
    int c0 = ks * 16 + (lane & 3) * 2;
    size_t row0 = (size_t)((r0 >> 5) * C_ + bid * 32 + (r0 & 31)) * H_;
    size_t row1 = (size_t)((r1 >> 5) * C_ + bid * 32 + (r1 & 31)) * H_;
    uint4 hi, lo;
    make_afrag(W_state, row0, row1, c0, hi, lo);
    g_WAh[idx] = hi;
    g_WAl[idx] = lo;
}

// x A-frags: rows m = b*T+t (natural row-major), 256 mtiles
__global__ void __launch_bounds__(256) xfrag_kernel(const float* __restrict__ x) {
    unsigned idx = blockIdx.x * 256 + threadIdx.x;    // < 256*32*32
    int mt   = idx >> 10;
    int k2   = (idx >> 5) & 31;
    int lane = idx & 31;
    int r0 = mt * 16 + (lane >> 2);
    int c0 = k2 * 16 + (lane & 3) * 2;
    uint4 hi, lo;
    make_afrag(x, (size_t)r0 * DIN_, (size_t)(r0 + 8) * DIN_, c0, hi, lo);
    g_xfH[idx] = hi;
    g_xfL[idx] = lo;
}

// W_in B-frags: npair covers n16 (two n8 tiles).
// uint4 = (b0@n, b1@n, b0@n+8, b1@n+8), n = npair*16 + lane/4,
// b0 = {k=c0,c0+1}, b1 = {k=c0+8,c0+9}
__global__ void __launch_bounds__(256) wifrag_kernel(const float* __restrict__ W_in) {
    unsigned idx = blockIdx.x * 256 + threadIdx.x;    // < 1024*32*32
    int np   = idx >> 10;
    int k2   = (idx >> 5) & 31;
    int lane = idx & 31;
    int n0 = np * 16 + (lane >> 2);
    int c0 = k2 * 16 + (lane & 3) * 2;
    float2 vA0 = *(const float2*)&W_in[(size_t)n0 * DIN_ + c0];
    float2 vA1 = *(const float2*)&W_in[(size_t)n0 * DIN_ + c0 + 8];
    float2 vB0 = *(const float2*)&W_in[(size_t)(n0 + 8) * DIN_ + c0];
    float2 vB1 = *(const float2*)&W_in[(size_t)(n0 + 8) * DIN_ + c0 + 8];
    float2 lA0, lA1, lB0, lB1;
    uint4 hi, lo;
    hi.x = bfsplit(vA0, lA0); hi.y = bfsplit(vA1, lA1);
    hi.z = bfsplit(vB0, lB0); hi.w = bfsplit(vB1, lB1);
    lo.x = bfpack(lA0); lo.y = bfpack(lA1); lo.z = bfpack(lB0); lo.w = bfpack(lB1);
    g_wfH[idx] = hi;
    g_wfL[idx] = lo;
}

// =====================================================================
// proj_in via HMMA: g_pi[m][j] = x[m][:] . W_in[j][:]
// grid (128 nblk, 32 mblk) x 256 threads. Warp: m32 x n64.
// Block (0,0) zeroes dataflow counters for this replay.
// =====================================================================
__global__ void __launch_bounds__(256) proj_in_mma_kernel() {
    const int tid = threadIdx.x;
    if (blockIdx.x == 0 && blockIdx.y == 0) {
        for (int i = tid; i < T_ * 8; i += 256)  g_cntA[i] = 0;
        for (int i = tid; i < T_ * 16; i += 256) g_cntB[i] = 0;
        for (int i = tid; i < T_; i += 256)      g_done[i] = 0;
        __threadfence();
    }

    const int w    = tid >> 5;
    const int lane = tid & 31;
    const int mgrp = w >> 1;             // 0..3 (m32 each)
    const int ngrp = w & 1;              // 0..1 (n64 each)
    const int mtile0 = blockIdx.y * 8 + mgrp * 2;    // of 256
    const int npair0 = blockIdx.x * 8 + ngrp * 4;    // of 1024

    float acc[2][8][4];
#pragma unroll
    for (int mi = 0; mi < 2; mi++)
#pragma unroll
        for (int nj = 0; nj < 8; nj++)
#pragma unroll
            for (int q = 0; q < 4; q++) acc[mi][nj][q] = 0.f;

    const uint4* xfH = g_xfH;
    const uint4* xfL = g_xfL;
    const uint4* wfH = g_wfH;
    const uint4* wfL = g_wfL;

#pragma unroll 2
    for (int k2 = 0; k2 < 32; k2++) {
        uint4 Ah[2], Al[2];
#pragma unroll
        for (int mi = 0; mi < 2; mi++) {
            Ah[mi] = __ldg(&xfH[((mtile0 + mi) * 32 + k2) * 32 + lane]);
            Al[mi] = __ldg(&xfL[((mtile0 + mi) * 32 + k2) * 32 + lane]);
        }
#pragma unroll
        for (int np = 0; np < 4; np++) {
            uint4 Bh = __ldg(&wfH[((npair0 + np) * 32 + k2) * 32 + lane]);
            uint4 Bl = __ldg(&wfL[((npair0 + np) * 32 + k2) * 32 + lane]);
#pragma unroll
            for (int mi = 0; mi < 2; mi++) {
                mma_bf16(acc[mi][np * 2],     Ah[mi], Bh.x, Bh.y);
                mma_bf16(acc[mi][np * 2 + 1], Ah[mi], Bh.z, Bh.w);
                mma_bf16(acc[mi][np * 2],     Ah[mi], Bl.x, Bl.y);
                mma_bf16(acc[mi][np * 2 + 1], Ah[mi], Bl.z, Bl.w);
                mma_bf16(acc[mi][np * 2],     Al[mi], Bh.x, Bh.y);
                mma_bf16(acc[mi][np * 2 + 1], Al[mi], Bh.z, Bh.w);
            }
        }
    }

    // write D: rows m, cols j
#pragma unroll
    for (int mi = 0; mi < 2; mi++) {
        int r0 = (mtile0 + mi) * 16 + (lane >> 2);
#pragma unroll
        for (int nj = 0; nj < 8; nj++) {
            int j0 = (npair0 + (nj >> 1)) * 16 + (nj & 1) * 8 + (lane & 3) * 2;
            *(float2*)&g_pi[(size_t)r0 * G_ + j0]       = make_float2(acc[mi][nj][0], acc[mi][nj][1]);
            *(float2*)&g_pi[(size_t)(r0 + 8) * G_ + j0] = make_float2(acc[mi][nj][2], acc[mi][nj][3]);
        }
    }
}

// =====================================================================
// scan: UNCHANGED from R13 (passing, 4840 us)
// =====================================================================
#define SBIG 0
#define SWPB 16384
#define SFLG 32768
#define SMEM_FLOATS 32772

__global__ void __launch_bounds__(NT, 1) scan_kernel(
    const int*   __restrict__ prev_idx,
    const float* __restrict__ prev_w,
    const float* __restrict__ b_state,
    const float* __restrict__ W_proj,
    float* __restrict__ out)
{
    extern __shared__ __align__(16) float sm[];
    float* sBig  = sm + SBIG;
    float* sD    = sm + SBIG;
    float* sWpB  = sm + SWPB;
    int*   s_flag = (int*)(sm + SFLG);
    const uint32_t smb = (uint32_t)__cvta_generic_to_shared(sm);

    const int tid = threadIdx.x;
    const int bid = blockIdx.x;
    const int w   = tid >> 5;
    const int b   = tid & 31;
    const int ht  = bid >> 3;
    const int ks  = bid & 7;
    const int ksA = bid >> 4;

    const int bE  = 2 * w + (b >> 4);
    const int ll  = b & 15;
    const int cE0 = bid * 32 + ll * 2;

    for (int r = 0; r < 32; r++) {
        int e  = r * NT + tid;
        int hl = e >> 9;
        int c  = e & 511;
        sWpB[c * 32 + hl] = __ldg(&W_proj[(size_t)(ht * 32 + hl) * C_ + ks * 512 + c]);
    }
    float bst[2][4];
#pragma unroll
    for (int ci = 0; ci < 2; ci++)
#pragma unroll
        for (int g = 0; g < 4; g++)
            bst[ci][g] = __ldg(&b_state[g * C_ + cE0 + ci]);
    __syncthreads();

    const uint4* WAh = g_WAh + (size_t)bid * 8192;
    const uint4* WAl = g_WAl + (size_t)bid * 8192;
    const int mt  = w & 7;
    const int ntp = w >> 3;

    for (int t = 0; t < T_; t++) {
        float wAv[P_];
        float2 pm2[P_];
#pragma unroll
        for (int p = 0; p < P_; p++) {
            int ip = __ldg(&prev_idx[(bE * T_ + t) * P_ + p]);
            wAv[p] = __ldg(&prev_w [(bE * T_ + t) * P_ + p]);
            pm2[p] = *(const float2*)&g_mem[((size_t)ip * B_ + bE) * C_ + cE0];
        }
        float2 pi2[4];
#pragma unroll
        for (int g = 0; g < 4; g++)
            pi2[g] = __ldg((const float2*)&g_pi[(size_t)(bE * T_ + t) * G_ + g * C_ + cE0]);

        if (t > 0) {
            if (tid == 0) SPIN_UNTIL(&g_done[t - 1], 16);
            __syncthreads();

            const uint4* pBf = g_pBf + (size_t)t * 4096;
            float d0[4] = {0.f, 0.f, 0.f, 0.f};
            float d1[4] = {0.f, 0.f, 0.f, 0.f};
#pragma unroll 4
            for (int k2 = 0; k2 < 32; k2++) {
                uint4 Ah = __ldg(&WAh[(k2 * 8 + mt) * 32 + b]);
                uint4 Al = __ldg(&WAl[(k2 * 8 + mt) * 32 + b]);
                uint4 Bh = __ldg(&pBf[((k2 * 2 + ntp) * 2 + 0) * 32 + b]);
                uint4 Bl = __ldg(&pBf[((k2 * 2 + ntp) * 2 + 1) * 32 + b]);
                mma_bf16(d0, Ah, Bh.x, Bh.y);
                mma_bf16(d1, Ah, Bh.z, Bh.w);
                mma_bf16(d0, Ah, Bl.x, Bl.y);
                mma_bf16(d1, Ah, Bl.z, Bl.w);
                mma_bf16(d0, Al, Bh.x, Bh.y);
                mma_bf16(d1, Al, Bh.z, Bh.w);
            }
            {
                int j0 = mt * 16 + (b >> 2);
                int bc = ntp * 16 + (b & 3) * 2;
                *(float2*)&sD[j0 * 34 + bc]           = make_float2(d0[0], d0[1]);
                *(float2*)&sD[(j0 + 8) * 34 + bc]     = make_float2(d0[2], d0[3]);
                *(float2*)&sD[j0 * 34 + bc + 8]       = make_float2(d1[0], d1[1]);
                *(float2*)&sD[(j0 + 8) * 34 + bc + 8] = make_float2(d1[2], d1[3]);
            }
            __syncthreads();
        }

        {
            float a2v[2], memv[2];
#pragma unroll
            for (int ci = 0; ci < 2; ci++) {
                float pmem = 0.f;
#pragma unroll
                for (int p = 0; p < P_; p++)
                    pmem += wAv[p] * ((ci == 0) ? pm2[p].x : pm2[p].y);
                float gv[4];
#pragma unroll
                for (int g = 0; g < 4; g++) {
                    float mmav = (t > 0) ? sD[(g * 32 + ll * 2 + ci) * 34 + bE] : 0.f;
                    float piv  = (ci == 0) ? pi2[g].x : pi2[g].y;
                    gv[g] = mmav + piv + bst[ci][g];
                }
                float ig = sigmoidf(gv[0]);
                float fg = sigmoidf(gv[1]);
                float mi = tanhf(gv[2]);
                float og = sigmoidf(gv[3]);
                memv[ci] = fminf(3.f, fmaxf(-3.f, ig * mi + fg * pmem));
                a2v[ci]  = og * tanhf(memv[ci]);
            }
            *(float2*)&g_mem[((size_t)t * B_ + bE) * C_ + cE0] = make_float2(memv[0], memv[1]);
            *(float2*)&g_a2[((size_t)bid * 16 + ll) * 64 + bE * 2] = make_float2(a2v[0], a2v[1]);
        }
        __syncthreads();
        if (tid == 0) atom_add_acqrel(&g_cntA[t * 8 + ksA], 1);

        if (tid == 0) SPIN_UNTIL(&g_cntA[t * 8 + ks], 16);
        __syncthreads();
#pragma unroll
        for (int r = 0; r < 8; r++) {
            int e = r * NT + tid;
            cp16(smb + SBIG * 4 + e * 16, (const char*)(g_a2 + ks * 16384) + e * 16);
        }
        CP_COMMIT();
        CP_WAIT0();
        __syncthreads();

        ull pac[8];
#pragma unroll
        for (int i = 0; i < 8; i++) pac[i] = 0ull;
        const int hhalf = w & 1;
        const int cch   = w >> 1;
#pragma unroll 4
        for (int cp = 0; cp < 32; cp++) {
            int cl2 = cch * 32 + cp;
            ull av = *(const ull*)(sBig + cl2 * 64 + b * 2);
            float alo, ahi;
            unpack2(av, alo, ahi);
            ull dlo = dup2(alo), dhi = dup2(ahi);
            int c0 = cl2 * 2;
            const float* w0p = sWpB + c0 * 32 + hhalf * 16;
            const float* w1p = w0p + 32;
#pragma unroll
            for (int q = 0; q < 4; q++) {
                ulonglong2 wa = ((const ulonglong2*)w0p)[q];
                ulonglong2 wb = ((const ulonglong2*)w1p)[q];
                pac[q * 2]     = fma2(wa.x, dlo, pac[q * 2]);
                pac[q * 2]     = fma2(wb.x, dhi, pac[q * 2]);
                pac[q * 2 + 1] = fma2(wa.y, dlo, pac[q * 2 + 1]);
                pac[q * 2 + 1] = fma2(wb.y, dhi, pac[q * 2 + 1]);
            }
        }
        __syncthreads();
#pragma unroll
        for (int hp = 0; hp < 8; hp++)
            *(ull*)(sBig + ((w * 8 + hp) * 64 + b * 2)) = pac[hp];
        __syncthreads();
#pragma unroll
        for (int r2 = 0; r2 < 2; r2++) {
            int o  = r2 * NT + tid;
            int hl = o >> 5, bb = o & 31;
            int ph   = hl >> 4;
            int hpin = (hl >> 1) & 7;
            int par  = hl & 1;
            float s = 0.f;
#pragma unroll
            for (int q = 0; q < 8; q++)
                s += sBig[((q * 2 + ph) * 8 + hpin) * 64 + bb * 2 + par];
            g_hp[bid * 1024 + hl * 32 + bb] = s;
        }
        __syncthreads();
        if (tid == 0) s_flag[0] = atom_add_acqrel(&g_cntB[t * 16 + ht], 1);
        __syncthreads();

        if (s_flag[0] == 7) {
            float part[2];
            int   ipg[2][P_];
            float wvg[2][P_];
#pragma unroll
            for (int r2 = 0; r2 < 2; r2++) {
                int o  = r2 * NT + tid;
                int hl = o >> 5, bb = o & 31;
                float s = 0.f;
#pragma unroll
                for (int q = 0; q < 8; q++)
                    s += __ldcg(&g_hp[(ht * 8 + q) * 1024 + hl * 32 + bb]);
                part[r2] = s;
                if (t < T_ - 1) {
#pragma unroll
                    for (int p = 0; p < P_; p++) {
                        ipg[r2][p] = __ldg(&prev_idx[(bb * T_ + t + 1) * P_ + p]);
                        wvg[r2][p] = __ldg(&prev_w [(bb * T_ + t + 1) * P_ + p]);
                    }
                }
            }
            float sv[2];
#pragma unroll
            for (int r2 = 0; r2 < 2; r2++) {
                int o  = r2 * NT + tid;
                int hl = o >> 5, bb = o & 31;
                float s = fminf(3.f, fmaxf(-3.f, part[r2]));
                sv[r2] = s;
                const int hg = ht * 32 + hl;
                g_st[((size_t)t * H_ + hg) * B_ + bb] = s;
                if (t < T_ - 1) {
                    float pv = 0.f;
#pragma unroll
                    for (int p = 0; p < P_; p++) {
                        float v = (ipg[r2][p] == t)
                                  ? s
                                  : __ldcg(&g_st[((size_t)ipg[r2][p] * H_ + hg) * B_ + bb]);
                        pv += wvg[r2][p] * v;
                    }
                    __nv_bfloat16 bh = __float2bfloat16(pv);
                    __nv_bfloat16 bl = __float2bfloat16(pv - __bfloat162float(bh));
                    int ksq  = hg >> 4;
                    int kin  = hg & 15;
                    int breg = kin >> 3;
                    int half = kin & 1;
                    int ntp2 = bb >> 4;
                    int ntl  = (bb >> 3) & 1;
                    int lane2 = (bb & 7) * 4 + ((kin & 7) >> 1);
                    char* basep = (char*)(g_pBf + (size_t)(t + 1) * 4096);
                    size_t off = ((size_t)((ksq * 2 + ntp2) * 2) * 32 + lane2) * 16
                                 + (ntl * 2 + breg) * 4 + half * 2;
                    *(__nv_bfloat16*)(basep + off)       = bh;
                    *(__nv_bfloat16*)(basep + off + 512) = bl;
                }
            }
            __syncthreads();
            if (tid == 0) atom_add_acqrel(&g_done[t], 1);
#pragma unroll
            for (int r2 = 0; r2 < 2; r2++) {
                int o  = r2 * NT + tid;
                int hl = o >> 5, bb = o & 31;
                out[((size_t)bb * T_ + t) * H_ + ht * 32 + hl] = sv[r2];
            }
        }
        __syncthreads();
    }
}

extern "C" void kernel_launch(void* const* d_in, const int* in_sizes, int n_in,
                              void* d_out, int out_size) {
    const float* x        = (const float*)d_in[0];
    const int*   prev_idx = (const int*)  d_in[1];
    const float* prev_w   = (const float*)d_in[2];
    const float* W_in     = (const float*)d_in[3];
    const float* W_state  = (const float*)d_in[4];
    const float* b_state  = (const float*)d_in[5];
    const float* W_proj   = (const float*)d_in[6];
    float* out = (float*)d_out;
    (void)in_sizes; (void)n_in; (void)out_size;

    const int smem = SMEM_FLOATS * (int)sizeof(float);
    cudaFuncSetAttribute(scan_kernel, cudaFuncAttributeMaxDynamicSharedMemorySize, smem);

    wfrag_kernel<<<(NBLK * 8192) / 256, 256>>>(W_state);
    xfrag_kernel<<<(256 * 1024) / 256, 256>>>(x);
    wifrag_kernel<<<(1024 * 1024) / 256, 256>>>(W_in);
    proj_in_mma_kernel<<<dim3(128, 32), 256>>>();
    scan_kernel<<<NBLK, NT, smem>>>(prev_idx, prev_w, b_state, W_proj, out);
}